// round 11
// baseline (speedup 1.0000x reference)
#include <cuda_runtime.h>
#include <cuda_fp16.h>

typedef unsigned long long ull;

#define HN 512
#define KN 64
#define NSAMP 16384
#define LRATE 0.001f
#define EPSF 1e-8f
#define WARPS 8
#define CHK 64
#define NCHUNK2 4                     // staging blocks of 128 rows
#define FH_H2 68                      // half2 per staged row (272 B); 68%32==4 -> conflict-free LDS.128
#define FBUF_B (CHK*272)              // 17408 B per 64-row sub-tile

// smem layout (float units)
#define FS_FLOATS   (2*CHK*FH_H2)     // 8704 (128 staged rows)
#define CS_OFF      FS_FLOATS
#define CS_WARP     576               // 16 quads * 36 floats (A at +0, B at +16, pad)
#define GB_OFF      (CS_OFF + WARPS*CS_WARP)
#define GB_WARP     768
#define WV_OFF      (GB_OFF + WARPS*GB_WARP)
#define SMEM_FLOATS (WV_OFF + WARPS*384)
#define SMEM_BYTES  (SMEM_FLOATS*4)   // 90112 B -> 2 CTAs/SM (reg-limited anyway)

__device__ __align__(16) unsigned g_Fh[HN*KN];        // [h][k] = half2(Bd, Bdd)
__device__ __align__(16) float4 g_PT4[(HN/2)*KN];     // [hp][k] = (pinv[k][2hp], B[2hp][k], pinv[k][2hp+1], B[2hp+1][k])
__device__ __align__(16) float2 g_Mp[KN*32];          // [kk*32+l] = (M[kk][l], M[kk][l+32])
__device__ __align__(16) float  g_CW[(NSAMP/2)*768];  // per-pair: [q<6][lane][4] = (c, -2*l1*wv) packed

// ---- packed f32x2 helpers ----
__device__ __forceinline__ ull ffma2(ull a, ull b, ull c){
    ull d; asm("fma.rn.f32x2 %0,%1,%2,%3;" : "=l"(d) : "l"(a), "l"(b), "l"(c)); return d;
}
__device__ __forceinline__ void funpack(ull u, float& x, float& y){
    asm("mov.b64 {%0,%1},%2;" : "=f"(x), "=f"(y) : "l"(u));
}
__device__ __forceinline__ ull fdup(float x){
    ull r; asm("mov.b64 %0,{%1,%1};" : "=l"(r) : "f"(x)); return r;
}
__device__ __forceinline__ ull pack2(float lo, float hi){
    ull r; asm("mov.b64 %0,{%1,%2};" : "=l"(r) : "f"(lo), "f"(hi)); return r;
}
// half2 bits -> packed f32x2
__device__ __forceinline__ ull h2f2(unsigned u){
    __half2 h = *(__half2*)&u;
    float2 f = __half22float2(h);
    return pack2(f.x, f.y);
}
// rsqrt on the fma/alu pipes: bit-hack seed + 2 Newton iterations (~4e-6 rel err)
__device__ __forceinline__ float rsqrt_fma(float x){
    float y = __uint_as_float(0x5f3759dfu - (__float_as_uint(x) >> 1));
    y = y * (1.5f - 0.5f*x*y*y);
    y = y * (1.5f - 0.5f*x*y*y);
    return y;
}

// K1: prep (blocks 0..127) + gram (blocks 128..191)
__global__ void prep_kernel(const float* __restrict__ B,
                            const float* __restrict__ Bd,
                            const float* __restrict__ Bdd,
                            const float* __restrict__ Bddd,
                            const float* __restrict__ Bpinv,
                            const float* __restrict__ lambdas)
{
    int bid = blockIdx.x, t = threadIdx.x;
    if (bid < 128) {
        int idx = bid*256 + t;
        __half2 hv = __halves2half2(__float2half(Bd[idx]), __float2half(Bdd[idx]));
        g_Fh[idx] = *(unsigned*)&hv;
        if (idx < (HN/2)*KN) {
            int hp = idx >> 6, k = idx & 63;
            int h0 = 2*hp, h1 = 2*hp + 1;
            g_PT4[idx] = make_float4(Bpinv[k*HN + h0], B[h0*KN + k],
                                     Bpinv[k*HN + h1], B[h1*KN + k]);
        }
    } else {
        __shared__ float pab[4][KN], paj[4][KN], Mrow[KN];
        int kk = bid - 128;
        int k2 = t & 63, part = t >> 6;
        // 4 independent accumulator streams -> MLP ~8 (was serial, latency-bound)
        float ab0=0.f, ab1=0.f, ab2=0.f, ab3=0.f;
        float aj0=0.f, aj1=0.f, aj2=0.f, aj3=0.f;
        int h0 = part*128;
        #pragma unroll 4
        for (int h = h0; h < h0 + 128; h += 4) {
            ab0 += B[(h+0)*KN + kk]    * B[(h+0)*KN + k2];
            ab1 += B[(h+1)*KN + kk]    * B[(h+1)*KN + k2];
            ab2 += B[(h+2)*KN + kk]    * B[(h+2)*KN + k2];
            ab3 += B[(h+3)*KN + kk]    * B[(h+3)*KN + k2];
            aj0 += Bddd[(h+0)*KN + kk] * Bddd[(h+0)*KN + k2];
            aj1 += Bddd[(h+1)*KN + kk] * Bddd[(h+1)*KN + k2];
            aj2 += Bddd[(h+2)*KN + kk] * Bddd[(h+2)*KN + k2];
            aj3 += Bddd[(h+3)*KN + kk] * Bddd[(h+3)*KN + k2];
        }
        pab[part][k2] = (ab0+ab1) + (ab2+ab3);
        paj[part][k2] = (aj0+aj1) + (aj2+aj3);
        __syncthreads();
        if (t < KN) {
            float sab = pab[0][t]+pab[1][t]+pab[2][t]+pab[3][t];
            float saj = paj[0][t]+paj[1][t]+paj[2][t]+paj[3][t];
            Mrow[t] = 2.f * (lambdas[0]*sab + lambdas[2]*saj);
        }
        __syncthreads();
        if (t < 32) g_Mp[kk*32 + t] = make_float2(Mrow[t], Mrow[t+32]);
    }
}

// K2: init matvecs hoisted out of the main kernel. One warp = 2 samples;
// computes c = Bpinv@r and -2*l1*(B^T r), stores packed per-lane float4s.
__global__ __launch_bounds__(256)
void init_kernel(const float* __restrict__ R_U,
                 const float* __restrict__ lambdas)
{
    const int w = threadIdx.x >> 5;
    const int l = threadIdx.x & 31;
    const int pair = blockIdx.x * WARPS + w;
    const int sA = pair*2, sB = sA + 1;
    const float l1 = lambdas[0];

    ull accw[2][2][3] = {{{0,0,0},{0,0,0}},{{0,0,0},{0,0,0}}};
    const float4* rpA = (const float4*)(R_U + (size_t)sA * (HN*3));
    const float4* rpB = (const float4*)(R_U + (size_t)sB * (HN*3));
    #pragma unroll 1
    for (int q = 0; q < HN/4; q++) {
        ulonglong2 u00 = *(const ulonglong2*)&g_PT4[(2*q  )*KN + l];
        ulonglong2 u01 = *(const ulonglong2*)&g_PT4[(2*q  )*KN + l + 32];
        ulonglong2 u10 = *(const ulonglong2*)&g_PT4[(2*q+1)*KN + l];
        ulonglong2 u11 = *(const ulonglong2*)&g_PT4[(2*q+1)*KN + l + 32];
        #pragma unroll
        for (int s = 0; s < 2; s++) {
            const float4* rp = s ? rpB : rpA;
            float4 r0 = rp[3*q], r1 = rp[3*q+1], r2 = rp[3*q+2];
            float rr[12] = {r0.x,r0.y,r0.z,r0.w, r1.x,r1.y,r1.z,r1.w, r2.x,r2.y,r2.z,r2.w};
            #pragma unroll
            for (int j = 0; j < 3; j++) {
                ull d0 = fdup(rr[j]);
                ull d1 = fdup(rr[3+j]);
                ull d2 = fdup(rr[6+j]);
                ull d3 = fdup(rr[9+j]);
                accw[s][0][j] = ffma2(u00.x, d0, accw[s][0][j]);
                accw[s][0][j] = ffma2(u00.y, d1, accw[s][0][j]);
                accw[s][0][j] = ffma2(u10.x, d2, accw[s][0][j]);
                accw[s][0][j] = ffma2(u10.y, d3, accw[s][0][j]);
                accw[s][1][j] = ffma2(u01.x, d0, accw[s][1][j]);
                accw[s][1][j] = ffma2(u01.y, d1, accw[s][1][j]);
                accw[s][1][j] = ffma2(u11.x, d2, accw[s][1][j]);
                accw[s][1][j] = ffma2(u11.y, d3, accw[s][1][j]);
            }
        }
    }
    float val[24];
    #pragma unroll
    for (int s = 0; s < 2; s++)
        #pragma unroll
        for (int k = 0; k < 2; k++)
            #pragma unroll
            for (int j = 0; j < 3; j++) {
                float cv, wvr;
                funpack(accw[s][k][j], cv, wvr);
                val[s*6 + k*3 + j]      = cv;
                val[12 + s*6 + k*3 + j] = -2.f*l1*wvr;
            }
    float4* cw = (float4*)(g_CW + (size_t)pair*768);
    #pragma unroll
    for (int q = 0; q < 6; q++)
        cw[q*32 + l] = make_float4(val[4*q], val[4*q+1], val[4*q+2], val[4*q+3]);
}

// Elementwise gradient of the power-law term wrt V and A (includes l2).
__device__ __forceinline__ void elemgrad(
    float v0, float v1, float v2,
    float a0, float a1, float a2,
    float aa, float bb, float l2, float* g)
{
    float vsq = v0*v0 + v1*v1 + v2*v2;
    float inv_vn = vsq > 0.f ? rsqrt_fma(vsq) : 0.f;
    float vn  = vsq * inv_vn;
    float vne = vn + EPSF;

    float cx = v1*a2 - v2*a1;
    float cy = v2*a0 - v0*a2;
    float cz = v0*a1 - v1*a0;
    float csq = cx*cx + cy*cy + cz*cz;
    float inv_cn = csq > 0.f ? rsqrtf(csq) : 0.f;
    float cn = csq * inv_cn;

    float inv_den = inv_vn * inv_vn * inv_vn;
    float kappa = cn * inv_den;

    float ks  = fminf(fmaxf(kappa, 1e-4f), 1e4f);
    float lpr = bb * __logf(ks);
    float lp  = fminf(fmaxf(lpr, -10.f), 10.f);
    float traw   = aa * __expf(lp);
    float target = fminf(fmaxf(traw, 1e-6f), 1e6f);

    float u   = vn - target;
    float gvn = 2.f * l2 * u;
    float gt  = (traw > 1e-6f && traw < 1e6f) ? (-2.f * l2 * u) : 0.f;
    float glk = ((lpr > -10.f && lpr < 10.f) ? gt * traw : 0.f) * bb;
    float gk  = (kappa > 1e-4f && kappa < 1e4f) ? glk : 0.f;
    float gcn  = gk * inv_cn;
    float gden = -gk * inv_den;
    gvn += gden * 3.f * vne * vne;

    float scr = gcn * inv_cn;
    float gc0 = scr * cx, gc1 = scr * cy, gc2 = scr * cz;
    float sV = gvn * inv_vn;
    g[0] = sV*v0 + a1*gc2 - a2*gc1;
    g[1] = sV*v1 + a2*gc0 - a0*gc2;
    g[2] = sV*v2 + a0*gc1 - a1*gc0;
    g[3] = gc1*v2 - gc2*v1;
    g[4] = gc2*v0 - gc0*v2;
    g[5] = gc0*v1 - gc1*v0;
}

// K3: main. One warp = 2 samples; 128 rows staged per barrier pair,
// two 64-row sub-tiles processed warp-locally between barriers.
__global__ __launch_bounds__(256, 2)
void inner_opt_kernel(const float* __restrict__ alpha,
                      const float* __restrict__ beta,
                      const float* __restrict__ lambdas,
                      float* __restrict__ out)
{
    extern __shared__ __align__(16) float smem[];
    char* FhBase = (char*)smem;                             // 128 rows of 272 B
    const int w = threadIdx.x >> 5;
    const int l = threadIdx.x & 31;
    float* Cq  = smem + CS_OFF + w*CS_WARP;                 // [quad][36]: A 12f @+0, B 12f @+16
    float2* GwA = (float2*)(smem + GB_OFF + w*GB_WARP);     // [j][h] (gV,gA)
    float2* GwB = GwA + 192;
    float*  Ws  = smem + WV_OFF + w*384;                    // [lane][12] -wv stash

    const int pair = blockIdx.x * WARPS + w;
    const int sA = pair*2;
    const int sB = sA + 1;
    const int k0 = l, k1 = l + 32;
    const int qa = l >> 2, la3 = (l & 3) * 3;               // C slot coords for k0 (k1: quad+8)

    const float l2 = lambdas[1];
    const float aaA = alpha[sA], bbA = beta[sA];
    const float aaB = alpha[sB], bbB = beta[sB];

    float c[2][2][3];   // [sample][k-half][j] kept in registers across all steps

    // ---- load precomputed (c, -wv) from init_kernel ----
    {
        const float4* cw = (const float4*)(g_CW + (size_t)pair*768);
        float val[24];
        #pragma unroll
        for (int q = 0; q < 6; q++) {
            float4 v = cw[q*32 + l];
            val[4*q+0] = v.x; val[4*q+1] = v.y; val[4*q+2] = v.z; val[4*q+3] = v.w;
        }
        #pragma unroll
        for (int s = 0; s < 2; s++)
            #pragma unroll
            for (int k = 0; k < 2; k++) {
                int slot = (qa + (k ? 8 : 0))*36 + s*16 + la3;
                #pragma unroll
                for (int j = 0; j < 3; j++) {
                    float cv = val[s*6 + k*3 + j];
                    c[s][k][j] = cv;
                    Cq[slot + j] = cv;
                    Ws[l*12 + s*6 + k*3 + j] = val[12 + s*6 + k*3 + j];
                }
            }
        __syncwarp();
    }

    for (int step = 0; step < 3; step++) {
        ull acc[2][2][3];   // packed (sum x*gV, sum y*gA); lo initialized to -wv
        #pragma unroll
        for (int s = 0; s < 2; s++)
            #pragma unroll
            for (int k = 0; k < 2; k++)
                #pragma unroll
                for (int j = 0; j < 3; j++)
                    acc[s][k][j] = pack2(Ws[l*12 + s*6 + k*3 + j], 0.f);

        for (int ch2 = 0; ch2 < NCHUNK2; ch2++) {
            __syncthreads();   // previous 128-row block fully consumed by all warps
            {  // stage 128 rows (32 KB) into padded rows
                const float4* src = (const float4*)(g_Fh + (ch2*2*CHK)*KN);
                int t = threadIdx.x;
                #pragma unroll
                for (int i = 0; i < 8; i++) {
                    int idx = t + 256*i;
                    int h = idx >> 4, q = idx & 15;
                    *(float4*)(FhBase + h*272 + q*16) = src[idx];
                }
            }
            __syncthreads();

            #pragma unroll 1
            for (int sub = 0; sub < 2; sub++) {
                const char* Fh = FhBase + sub*FBUF_B;

                // ---- Phase A: forward (V,A) for 2 samples + elementwise grads ----
                {
                    const char* r0 = Fh + l*272;
                    const char* r1 = Fh + (l+32)*272;
                    ull va[2][2][3] = {{{0,0,0},{0,0,0}},{{0,0,0},{0,0,0}}};
                    #pragma unroll 2
                    for (int q = 0; q < 16; q++) {
                        ulonglong2 u0 = *(const ulonglong2*)(r0 + q*16);
                        ulonglong2 u1 = *(const ulonglong2*)(r1 + q*16);
                        ull x0[4], x1[4];
                        x0[0] = h2f2((unsigned)u0.x); x0[1] = h2f2((unsigned)(u0.x >> 32));
                        x0[2] = h2f2((unsigned)u0.y); x0[3] = h2f2((unsigned)(u0.y >> 32));
                        x1[0] = h2f2((unsigned)u1.x); x1[1] = h2f2((unsigned)(u1.x >> 32));
                        x1[2] = h2f2((unsigned)u1.y); x1[3] = h2f2((unsigned)(u1.y >> 32));
                        const float* cqp = Cq + q*36;
                        #pragma unroll
                        for (int s = 0; s < 2; s++) {
                            float4 c0 = *(const float4*)(cqp + s*16);
                            float4 c1 = *(const float4*)(cqp + s*16 + 4);
                            float4 c2 = *(const float4*)(cqp + s*16 + 8);
                            float cf[12] = {c0.x,c0.y,c0.z,c0.w,
                                            c1.x,c1.y,c1.z,c1.w,
                                            c2.x,c2.y,c2.z,c2.w};
                            #pragma unroll
                            for (int i = 0; i < 4; i++) {
                                ull d0 = fdup(cf[i*3+0]);
                                ull d1 = fdup(cf[i*3+1]);
                                ull d2 = fdup(cf[i*3+2]);
                                va[s][0][0] = ffma2(x0[i], d0, va[s][0][0]);
                                va[s][0][1] = ffma2(x0[i], d1, va[s][0][1]);
                                va[s][0][2] = ffma2(x0[i], d2, va[s][0][2]);
                                va[s][1][0] = ffma2(x1[i], d0, va[s][1][0]);
                                va[s][1][1] = ffma2(x1[i], d1, va[s][1][1]);
                                va[s][1][2] = ffma2(x1[i], d2, va[s][1][2]);
                            }
                        }
                    }
                    float V[3], A[3], g[6];
                    #pragma unroll
                    for (int s = 0; s < 2; s++) {
                        float2* Gw = s ? GwB : GwA;
                        float aa = s ? aaB : aaA;
                        float bb = s ? bbB : bbA;
                        #pragma unroll
                        for (int r = 0; r < 2; r++) {
                            funpack(va[s][r][0], V[0], A[0]);
                            funpack(va[s][r][1], V[1], A[1]);
                            funpack(va[s][r][2], V[2], A[2]);
                            elemgrad(V[0],V[1],V[2], A[0],A[1],A[2], aa,bb,l2, g);
                            int hh = l + 32*r;
                            #pragma unroll
                            for (int j = 0; j < 3; j++)
                                Gw[j*CHK + hh] = make_float2(g[j], g[3+j]);
                        }
                    }
                }
                __syncwarp();

                // ---- Phase B: dC accumulation (fp16 column reads of the same tile) ----
                {
                    const ulonglong2* pgA0 = (const ulonglong2*)(GwA);
                    const ulonglong2* pgA1 = (const ulonglong2*)(GwA + CHK);
                    const ulonglong2* pgA2 = (const ulonglong2*)(GwA + 2*CHK);
                    const ulonglong2* pgB0 = (const ulonglong2*)(GwB);
                    const ulonglong2* pgB1 = (const ulonglong2*)(GwB + CHK);
                    const ulonglong2* pgB2 = (const ulonglong2*)(GwB + 2*CHK);
                    #pragma unroll 2
                    for (int hp = 0; hp < 32; hp++) {
                        const char* rowA = Fh + (2*hp)*272;
                        const char* rowB = Fh + (2*hp+1)*272;
                        ull t00 = h2f2(*(const unsigned*)(rowA + l*4));
                        ull t01 = h2f2(*(const unsigned*)(rowA + (l+32)*4));
                        ull t10 = h2f2(*(const unsigned*)(rowB + l*4));
                        ull t11 = h2f2(*(const unsigned*)(rowB + (l+32)*4));
                        ulonglong2 p0 = pgA0[hp], p1 = pgA1[hp], p2 = pgA2[hp];
                        acc[0][0][0] = ffma2(t00, p0.x, acc[0][0][0]);
                        acc[0][0][1] = ffma2(t00, p1.x, acc[0][0][1]);
                        acc[0][0][2] = ffma2(t00, p2.x, acc[0][0][2]);
                        acc[0][1][0] = ffma2(t01, p0.x, acc[0][1][0]);
                        acc[0][1][1] = ffma2(t01, p1.x, acc[0][1][1]);
                        acc[0][1][2] = ffma2(t01, p2.x, acc[0][1][2]);
                        acc[0][0][0] = ffma2(t10, p0.y, acc[0][0][0]);
                        acc[0][0][1] = ffma2(t10, p1.y, acc[0][0][1]);
                        acc[0][0][2] = ffma2(t10, p2.y, acc[0][0][2]);
                        acc[0][1][0] = ffma2(t11, p0.y, acc[0][1][0]);
                        acc[0][1][1] = ffma2(t11, p1.y, acc[0][1][1]);
                        acc[0][1][2] = ffma2(t11, p2.y, acc[0][1][2]);
                        ulonglong2 q0 = pgB0[hp], q1 = pgB1[hp], q2 = pgB2[hp];
                        acc[1][0][0] = ffma2(t00, q0.x, acc[1][0][0]);
                        acc[1][0][1] = ffma2(t00, q1.x, acc[1][0][1]);
                        acc[1][0][2] = ffma2(t00, q2.x, acc[1][0][2]);
                        acc[1][1][0] = ffma2(t01, q0.x, acc[1][1][0]);
                        acc[1][1][1] = ffma2(t01, q1.x, acc[1][1][1]);
                        acc[1][1][2] = ffma2(t01, q2.x, acc[1][1][2]);
                        acc[1][0][0] = ffma2(t10, q0.y, acc[1][0][0]);
                        acc[1][0][1] = ffma2(t10, q1.y, acc[1][0][1]);
                        acc[1][0][2] = ffma2(t10, q2.y, acc[1][0][2]);
                        acc[1][1][0] = ffma2(t11, q0.y, acc[1][1][0]);
                        acc[1][1][1] = ffma2(t11, q1.y, acc[1][1][1]);
                        acc[1][1][2] = ffma2(t11, q2.y, acc[1][1][2]);
                    }
                }
                __syncwarp();
            }
        }

        // ---- Phase C: mc = M @ C for both samples, then SGD update ----
        ull mca[2][3] = {{0,0,0},{0,0,0}};
        {
            #pragma unroll 2
            for (int q = 0; q < 16; q++) {
                const float* cqp = Cq + q*36;
                float4 a0 = *(const float4*)(cqp);
                float4 a1 = *(const float4*)(cqp + 4);
                float4 a2 = *(const float4*)(cqp + 8);
                float4 b0 = *(const float4*)(cqp + 16);
                float4 b1 = *(const float4*)(cqp + 20);
                float4 b2 = *(const float4*)(cqp + 24);
                float cA[12] = {a0.x,a0.y,a0.z,a0.w, a1.x,a1.y,a1.z,a1.w, a2.x,a2.y,a2.z,a2.w};
                float cB[12] = {b0.x,b0.y,b0.z,b0.w, b1.x,b1.y,b1.z,b1.w, b2.x,b2.y,b2.z,b2.w};
                #pragma unroll
                for (int i = 0; i < 4; i++) {
                    int kk = 4*q + i;
                    ull pm = *(const ull*)&g_Mp[kk*32 + l];
                    mca[0][0] = ffma2(pm, fdup(cA[i*3+0]), mca[0][0]);
                    mca[0][1] = ffma2(pm, fdup(cA[i*3+1]), mca[0][1]);
                    mca[0][2] = ffma2(pm, fdup(cA[i*3+2]), mca[0][2]);
                    mca[1][0] = ffma2(pm, fdup(cB[i*3+0]), mca[1][0]);
                    mca[1][1] = ffma2(pm, fdup(cB[i*3+1]), mca[1][1]);
                    mca[1][2] = ffma2(pm, fdup(cB[i*3+2]), mca[1][2]);
                }
            }
        }
        __syncwarp();   // all lanes done reading C before update
        #pragma unroll
        for (int s = 0; s < 2; s++)
            #pragma unroll
            for (int k = 0; k < 2; k++) {
                int slot = (qa + (k ? 8 : 0))*36 + s*16 + la3;
                #pragma unroll
                for (int j = 0; j < 3; j++) {
                    float dlo, dhi, m0, m1;
                    funpack(acc[s][k][j], dlo, dhi);    // dlo includes -wv
                    funpack(mca[s][j], m0, m1);
                    float m = k ? m1 : m0;
                    c[s][k][j] -= LRATE * (dlo + dhi + m);
                    Cq[slot + j] = c[s][k][j];
                }
            }
        __syncwarp();
    }

    // ---- output (from registers) ----
    #pragma unroll
    for (int s = 0; s < 2; s++) {
        float* op = out + (size_t)(sA + s) * (KN*3);
        #pragma unroll
        for (int j = 0; j < 3; j++) {
            op[k0*3 + j] = c[s][0][j];
            op[k1*3 + j] = c[s][1][j];
        }
    }
}

extern "C" void kernel_launch(void* const* d_in, const int* in_sizes, int n_in,
                              void* d_out, int out_size)
{
    const float* R_U     = (const float*)d_in[0];
    const float* alpha   = (const float*)d_in[1];
    const float* beta    = (const float*)d_in[2];
    const float* lambdas = (const float*)d_in[3];
    const float* B       = (const float*)d_in[4];
    const float* Bd      = (const float*)d_in[5];
    const float* Bdd     = (const float*)d_in[6];
    const float* Bddd    = (const float*)d_in[7];
    const float* Bpinv   = (const float*)d_in[8];

    cudaFuncSetAttribute(inner_opt_kernel,
                         cudaFuncAttributeMaxDynamicSharedMemorySize, SMEM_BYTES);

    prep_kernel<<<192, 256>>>(B, Bd, Bdd, Bddd, Bpinv, lambdas);
    init_kernel<<<NSAMP/(WARPS*2), 256>>>(R_U, lambdas);
    inner_opt_kernel<<<NSAMP/(WARPS*2), 256, SMEM_BYTES>>>(
        alpha, beta, lambdas, (float*)d_out);
}

// round 12
// speedup vs baseline: 1.0298x; 1.0298x over previous
#include <cuda_runtime.h>
#include <cuda_fp16.h>

typedef unsigned long long ull;

#define HN 512
#define KN 64
#define NSAMP 16384
#define LRATE 0.001f
#define EPSF 1e-8f
#define WARPS 8
#define CHK 64
#define NCHUNK (HN/CHK)
#define FH_H2 68                      // half2 per staged row (272 B); 68%32==4 -> conflict-free LDS.128

// smem layout (float units)
#define FS_FLOATS   (CHK*FH_H2)       // 4352
#define CS_OFF      FS_FLOATS
#define CS_WARP     576               // 16 quads * 36 floats (A at +0, B at +16, pad)
#define GB_OFF      (CS_OFF + WARPS*CS_WARP)
#define GB_WARP     768
#define WV_OFF      (GB_OFF + WARPS*GB_WARP)
#define SMEM_FLOATS (WV_OFF + WARPS*384)
#define SMEM_BYTES  (SMEM_FLOATS*4)   // 72704 B -> 2 CTAs/SM

__device__ __align__(16) unsigned g_Fh[HN*KN];        // [h][k] = half2(Bd, Bdd)
__device__ __align__(16) float4 g_PT4[(HN/2)*KN];     // [hp][k] = (pinv[k][2hp], B[2hp][k], pinv[k][2hp+1], B[2hp+1][k])
__device__ __align__(16) float2 g_Mp[KN*32];          // [kk*32+l] = (M[kk][l], M[kk][l+32])
__device__ __align__(16) float  g_CW[(NSAMP/2)*768];  // per-pair: [q<6][lane][4] = (c, -2*l1*wv) packed

// ---- packed f32x2 helpers ----
__device__ __forceinline__ ull ffma2(ull a, ull b, ull c){
    ull d; asm("fma.rn.f32x2 %0,%1,%2,%3;" : "=l"(d) : "l"(a), "l"(b), "l"(c)); return d;
}
__device__ __forceinline__ void funpack(ull u, float& x, float& y){
    asm("mov.b64 {%0,%1},%2;" : "=f"(x), "=f"(y) : "l"(u));
}
__device__ __forceinline__ ull fdup(float x){
    ull r; asm("mov.b64 %0,{%1,%1};" : "=l"(r) : "f"(x)); return r;
}
__device__ __forceinline__ ull pack2(float lo, float hi){
    ull r; asm("mov.b64 %0,{%1,%2};" : "=l"(r) : "f"(lo), "f"(hi)); return r;
}
// half2 bits -> packed f32x2
__device__ __forceinline__ ull h2f2(unsigned u){
    __half2 h = *(__half2*)&u;
    float2 f = __half22float2(h);
    return pack2(f.x, f.y);
}
// rsqrt on the fma/alu pipes: bit-hack seed + 2 Newton iterations (~4e-6 rel err)
__device__ __forceinline__ float rsqrt_fma(float x){
    float y = __uint_as_float(0x5f3759dfu - (__float_as_uint(x) >> 1));
    y = y * (1.5f - 0.5f*x*y*y);
    y = y * (1.5f - 0.5f*x*y*y);
    return y;
}

// K1: prep (blocks 0..127) + gram (blocks 128..191, ILP-8 accumulators)
__global__ void prep_kernel(const float* __restrict__ B,
                            const float* __restrict__ Bd,
                            const float* __restrict__ Bdd,
                            const float* __restrict__ Bddd,
                            const float* __restrict__ Bpinv,
                            const float* __restrict__ lambdas)
{
    int bid = blockIdx.x, t = threadIdx.x;
    if (bid < 128) {
        int idx = bid*256 + t;
        __half2 hv = __halves2half2(__float2half(Bd[idx]), __float2half(Bdd[idx]));
        g_Fh[idx] = *(unsigned*)&hv;
        if (idx < (HN/2)*KN) {
            int hp = idx >> 6, k = idx & 63;
            int h0 = 2*hp, h1 = 2*hp + 1;
            g_PT4[idx] = make_float4(Bpinv[k*HN + h0], B[h0*KN + k],
                                     Bpinv[k*HN + h1], B[h1*KN + k]);
        }
    } else {
        __shared__ float pab[4][KN], paj[4][KN], Mrow[KN];
        int kk = bid - 128;
        int k2 = t & 63, part = t >> 6;
        // 4 independent accumulator streams per product -> MLP ~8
        float ab0=0.f, ab1=0.f, ab2=0.f, ab3=0.f;
        float aj0=0.f, aj1=0.f, aj2=0.f, aj3=0.f;
        int h0 = part*128;
        #pragma unroll 4
        for (int h = h0; h < h0 + 128; h += 4) {
            ab0 += B[(h+0)*KN + kk]    * B[(h+0)*KN + k2];
            ab1 += B[(h+1)*KN + kk]    * B[(h+1)*KN + k2];
            ab2 += B[(h+2)*KN + kk]    * B[(h+2)*KN + k2];
            ab3 += B[(h+3)*KN + kk]    * B[(h+3)*KN + k2];
            aj0 += Bddd[(h+0)*KN + kk] * Bddd[(h+0)*KN + k2];
            aj1 += Bddd[(h+1)*KN + kk] * Bddd[(h+1)*KN + k2];
            aj2 += Bddd[(h+2)*KN + kk] * Bddd[(h+2)*KN + k2];
            aj3 += Bddd[(h+3)*KN + kk] * Bddd[(h+3)*KN + k2];
        }
        pab[part][k2] = (ab0+ab1) + (ab2+ab3);
        paj[part][k2] = (aj0+aj1) + (aj2+aj3);
        __syncthreads();
        if (t < KN) {
            float sab = pab[0][t]+pab[1][t]+pab[2][t]+pab[3][t];
            float saj = paj[0][t]+paj[1][t]+paj[2][t]+paj[3][t];
            Mrow[t] = 2.f * (lambdas[0]*sab + lambdas[2]*saj);
        }
        __syncthreads();
        if (t < 32) g_Mp[kk*32 + t] = make_float2(Mrow[t], Mrow[t+32]);
    }
}

// K2: init matvecs hoisted out of the main kernel. One warp = 2 samples;
// computes c = Bpinv@r and -2*l1*(B^T r), stores packed per-lane float4s.
__global__ __launch_bounds__(256)
void init_kernel(const float* __restrict__ R_U,
                 const float* __restrict__ lambdas)
{
    const int w = threadIdx.x >> 5;
    const int l = threadIdx.x & 31;
    const int pair = blockIdx.x * WARPS + w;
    const int sA = pair*2, sB = sA + 1;
    const float l1 = lambdas[0];

    ull accw[2][2][3] = {{{0,0,0},{0,0,0}},{{0,0,0},{0,0,0}}};
    const float4* rpA = (const float4*)(R_U + (size_t)sA * (HN*3));
    const float4* rpB = (const float4*)(R_U + (size_t)sB * (HN*3));
    #pragma unroll 1
    for (int q = 0; q < HN/4; q++) {
        ulonglong2 u00 = *(const ulonglong2*)&g_PT4[(2*q  )*KN + l];
        ulonglong2 u01 = *(const ulonglong2*)&g_PT4[(2*q  )*KN + l + 32];
        ulonglong2 u10 = *(const ulonglong2*)&g_PT4[(2*q+1)*KN + l];
        ulonglong2 u11 = *(const ulonglong2*)&g_PT4[(2*q+1)*KN + l + 32];
        #pragma unroll
        for (int s = 0; s < 2; s++) {
            const float4* rp = s ? rpB : rpA;
            float4 r0 = rp[3*q], r1 = rp[3*q+1], r2 = rp[3*q+2];
            float rr[12] = {r0.x,r0.y,r0.z,r0.w, r1.x,r1.y,r1.z,r1.w, r2.x,r2.y,r2.z,r2.w};
            #pragma unroll
            for (int j = 0; j < 3; j++) {
                ull d0 = fdup(rr[j]);
                ull d1 = fdup(rr[3+j]);
                ull d2 = fdup(rr[6+j]);
                ull d3 = fdup(rr[9+j]);
                accw[s][0][j] = ffma2(u00.x, d0, accw[s][0][j]);
                accw[s][0][j] = ffma2(u00.y, d1, accw[s][0][j]);
                accw[s][0][j] = ffma2(u10.x, d2, accw[s][0][j]);
                accw[s][0][j] = ffma2(u10.y, d3, accw[s][0][j]);
                accw[s][1][j] = ffma2(u01.x, d0, accw[s][1][j]);
                accw[s][1][j] = ffma2(u01.y, d1, accw[s][1][j]);
                accw[s][1][j] = ffma2(u11.x, d2, accw[s][1][j]);
                accw[s][1][j] = ffma2(u11.y, d3, accw[s][1][j]);
            }
        }
    }
    float val[24];
    #pragma unroll
    for (int s = 0; s < 2; s++)
        #pragma unroll
        for (int k = 0; k < 2; k++)
            #pragma unroll
            for (int j = 0; j < 3; j++) {
                float cv, wvr;
                funpack(accw[s][k][j], cv, wvr);
                val[s*6 + k*3 + j]      = cv;
                val[12 + s*6 + k*3 + j] = -2.f*l1*wvr;
            }
    float4* cw = (float4*)(g_CW + (size_t)pair*768);
    #pragma unroll
    for (int q = 0; q < 6; q++)
        cw[q*32 + l] = make_float4(val[4*q], val[4*q+1], val[4*q+2], val[4*q+3]);
}

// Elementwise gradient of the power-law term wrt V and A (includes l2).
__device__ __forceinline__ void elemgrad(
    float v0, float v1, float v2,
    float a0, float a1, float a2,
    float aa, float bb, float l2, float* g)
{
    float vsq = v0*v0 + v1*v1 + v2*v2;
    float inv_vn = vsq > 0.f ? rsqrt_fma(vsq) : 0.f;
    float vn  = vsq * inv_vn;
    float vne = vn + EPSF;

    float cx = v1*a2 - v2*a1;
    float cy = v2*a0 - v0*a2;
    float cz = v0*a1 - v1*a0;
    float csq = cx*cx + cy*cy + cz*cz;
    float inv_cn = csq > 0.f ? rsqrtf(csq) : 0.f;
    float cn = csq * inv_cn;

    float inv_den = inv_vn * inv_vn * inv_vn;
    float kappa = cn * inv_den;

    float ks  = fminf(fmaxf(kappa, 1e-4f), 1e4f);
    float lpr = bb * __logf(ks);
    float lp  = fminf(fmaxf(lpr, -10.f), 10.f);
    float traw   = aa * __expf(lp);
    float target = fminf(fmaxf(traw, 1e-6f), 1e6f);

    float u   = vn - target;
    float gvn = 2.f * l2 * u;
    float gt  = (traw > 1e-6f && traw < 1e6f) ? (-2.f * l2 * u) : 0.f;
    float glk = ((lpr > -10.f && lpr < 10.f) ? gt * traw : 0.f) * bb;
    float gk  = (kappa > 1e-4f && kappa < 1e4f) ? glk : 0.f;
    float gcn  = gk * inv_cn;
    float gden = -gk * inv_den;
    gvn += gden * 3.f * vne * vne;

    float scr = gcn * inv_cn;
    float gc0 = scr * cx, gc1 = scr * cy, gc2 = scr * cz;
    float sV = gvn * inv_vn;
    g[0] = sV*v0 + a1*gc2 - a2*gc1;
    g[1] = sV*v1 + a2*gc0 - a0*gc2;
    g[2] = sV*v2 + a0*gc1 - a1*gc0;
    g[3] = gc1*v2 - gc2*v1;
    g[4] = gc2*v0 - gc0*v2;
    g[5] = gc0*v1 - gc1*v0;
}

// K3: main (R10 structure — 64-row chunks, 2 barriers/chunk; proven fastest).
__global__ __launch_bounds__(256, 2)
void inner_opt_kernel(const float* __restrict__ alpha,
                      const float* __restrict__ beta,
                      const float* __restrict__ lambdas,
                      float* __restrict__ out)
{
    extern __shared__ __align__(16) float smem[];
    char* Fh = (char*)smem;                                 // [CHK] rows of 272 B (68 half2)
    const int w = threadIdx.x >> 5;
    const int l = threadIdx.x & 31;
    float* Cq  = smem + CS_OFF + w*CS_WARP;                 // [quad][36]: A 12f @+0, B 12f @+16
    float2* GwA = (float2*)(smem + GB_OFF + w*GB_WARP);     // [j][h] (gV,gA)
    float2* GwB = GwA + 192;
    float*  Ws  = smem + WV_OFF + w*384;                    // [lane][12] -wv stash

    const int pair = blockIdx.x * WARPS + w;
    const int sA = pair*2;
    const int sB = sA + 1;
    const int k0 = l, k1 = l + 32;
    const int qa = l >> 2, la3 = (l & 3) * 3;               // C slot coords for k0 (k1: quad+8)

    const float l2 = lambdas[1];
    const float aaA = alpha[sA], bbA = beta[sA];
    const float aaB = alpha[sB], bbB = beta[sB];

    float c[2][2][3];   // [sample][k-half][j] kept in registers across all steps

    // ---- load precomputed (c, -wv) from init_kernel ----
    {
        const float4* cw = (const float4*)(g_CW + (size_t)pair*768);
        float val[24];
        #pragma unroll
        for (int q = 0; q < 6; q++) {
            float4 v = cw[q*32 + l];
            val[4*q+0] = v.x; val[4*q+1] = v.y; val[4*q+2] = v.z; val[4*q+3] = v.w;
        }
        #pragma unroll
        for (int s = 0; s < 2; s++)
            #pragma unroll
            for (int k = 0; k < 2; k++) {
                int slot = (qa + (k ? 8 : 0))*36 + s*16 + la3;
                #pragma unroll
                for (int j = 0; j < 3; j++) {
                    float cv = val[s*6 + k*3 + j];
                    c[s][k][j] = cv;
                    Cq[slot + j] = cv;
                    Ws[l*12 + s*6 + k*3 + j] = val[12 + s*6 + k*3 + j];
                }
            }
        __syncwarp();
    }

    for (int step = 0; step < 3; step++) {
        ull acc[2][2][3];   // packed (sum x*gV, sum y*gA); lo initialized to -wv
        #pragma unroll
        for (int s = 0; s < 2; s++)
            #pragma unroll
            for (int k = 0; k < 2; k++)
                #pragma unroll
                for (int j = 0; j < 3; j++)
                    acc[s][k][j] = pack2(Ws[l*12 + s*6 + k*3 + j], 0.f);

        for (int ch = 0; ch < NCHUNK; ch++) {
            const int base = ch * CHK;
            __syncthreads();   // previous chunk fully consumed by all warps
            {  // stage fp16 tile (16 KB) into padded rows
                const float4* src = (const float4*)(g_Fh + base*KN);
                int t = threadIdx.x;
                #pragma unroll
                for (int i = 0; i < 4; i++) {
                    int idx = t + 256*i;
                    int h = idx >> 4, q = idx & 15;
                    *(float4*)(Fh + h*272 + q*16) = src[idx];
                }
            }
            __syncthreads();

            // ---- Phase A: forward (V,A) for 2 samples + elementwise grads ----
            {
                const char* r0 = Fh + l*272;
                const char* r1 = Fh + (l+32)*272;
                ull va[2][2][3] = {{{0,0,0},{0,0,0}},{{0,0,0},{0,0,0}}};
                #pragma unroll 2
                for (int q = 0; q < 16; q++) {
                    ulonglong2 u0 = *(const ulonglong2*)(r0 + q*16);
                    ulonglong2 u1 = *(const ulonglong2*)(r1 + q*16);
                    ull x0[4], x1[4];
                    x0[0] = h2f2((unsigned)u0.x); x0[1] = h2f2((unsigned)(u0.x >> 32));
                    x0[2] = h2f2((unsigned)u0.y); x0[3] = h2f2((unsigned)(u0.y >> 32));
                    x1[0] = h2f2((unsigned)u1.x); x1[1] = h2f2((unsigned)(u1.x >> 32));
                    x1[2] = h2f2((unsigned)u1.y); x1[3] = h2f2((unsigned)(u1.y >> 32));
                    const float* cqp = Cq + q*36;
                    #pragma unroll
                    for (int s = 0; s < 2; s++) {
                        float4 c0 = *(const float4*)(cqp + s*16);
                        float4 c1 = *(const float4*)(cqp + s*16 + 4);
                        float4 c2 = *(const float4*)(cqp + s*16 + 8);
                        float cf[12] = {c0.x,c0.y,c0.z,c0.w,
                                        c1.x,c1.y,c1.z,c1.w,
                                        c2.x,c2.y,c2.z,c2.w};
                        #pragma unroll
                        for (int i = 0; i < 4; i++) {
                            ull d0 = fdup(cf[i*3+0]);
                            ull d1 = fdup(cf[i*3+1]);
                            ull d2 = fdup(cf[i*3+2]);
                            va[s][0][0] = ffma2(x0[i], d0, va[s][0][0]);
                            va[s][0][1] = ffma2(x0[i], d1, va[s][0][1]);
                            va[s][0][2] = ffma2(x0[i], d2, va[s][0][2]);
                            va[s][1][0] = ffma2(x1[i], d0, va[s][1][0]);
                            va[s][1][1] = ffma2(x1[i], d1, va[s][1][1]);
                            va[s][1][2] = ffma2(x1[i], d2, va[s][1][2]);
                        }
                    }
                }
                float V[3], A[3], g[6];
                #pragma unroll
                for (int s = 0; s < 2; s++) {
                    float2* Gw = s ? GwB : GwA;
                    float aa = s ? aaB : aaA;
                    float bb = s ? bbB : bbA;
                    #pragma unroll
                    for (int r = 0; r < 2; r++) {
                        funpack(va[s][r][0], V[0], A[0]);
                        funpack(va[s][r][1], V[1], A[1]);
                        funpack(va[s][r][2], V[2], A[2]);
                        elemgrad(V[0],V[1],V[2], A[0],A[1],A[2], aa,bb,l2, g);
                        int hh = l + 32*r;
                        #pragma unroll
                        for (int j = 0; j < 3; j++)
                            Gw[j*CHK + hh] = make_float2(g[j], g[3+j]);
                    }
                }
            }
            __syncwarp();

            // ---- Phase B: dC accumulation (fp16 column reads of the same tile) ----
            {
                const ulonglong2* pgA0 = (const ulonglong2*)(GwA);
                const ulonglong2* pgA1 = (const ulonglong2*)(GwA + CHK);
                const ulonglong2* pgA2 = (const ulonglong2*)(GwA + 2*CHK);
                const ulonglong2* pgB0 = (const ulonglong2*)(GwB);
                const ulonglong2* pgB1 = (const ulonglong2*)(GwB + CHK);
                const ulonglong2* pgB2 = (const ulonglong2*)(GwB + 2*CHK);
                #pragma unroll 2
                for (int hp = 0; hp < 32; hp++) {
                    const char* rowA = Fh + (2*hp)*272;
                    const char* rowB = Fh + (2*hp+1)*272;
                    ull t00 = h2f2(*(const unsigned*)(rowA + l*4));
                    ull t01 = h2f2(*(const unsigned*)(rowA + (l+32)*4));
                    ull t10 = h2f2(*(const unsigned*)(rowB + l*4));
                    ull t11 = h2f2(*(const unsigned*)(rowB + (l+32)*4));
                    ulonglong2 p0 = pgA0[hp], p1 = pgA1[hp], p2 = pgA2[hp];
                    acc[0][0][0] = ffma2(t00, p0.x, acc[0][0][0]);
                    acc[0][0][1] = ffma2(t00, p1.x, acc[0][0][1]);
                    acc[0][0][2] = ffma2(t00, p2.x, acc[0][0][2]);
                    acc[0][1][0] = ffma2(t01, p0.x, acc[0][1][0]);
                    acc[0][1][1] = ffma2(t01, p1.x, acc[0][1][1]);
                    acc[0][1][2] = ffma2(t01, p2.x, acc[0][1][2]);
                    acc[0][0][0] = ffma2(t10, p0.y, acc[0][0][0]);
                    acc[0][0][1] = ffma2(t10, p1.y, acc[0][0][1]);
                    acc[0][0][2] = ffma2(t10, p2.y, acc[0][0][2]);
                    acc[0][1][0] = ffma2(t11, p0.y, acc[0][1][0]);
                    acc[0][1][1] = ffma2(t11, p1.y, acc[0][1][1]);
                    acc[0][1][2] = ffma2(t11, p2.y, acc[0][1][2]);
                    ulonglong2 q0 = pgB0[hp], q1 = pgB1[hp], q2 = pgB2[hp];
                    acc[1][0][0] = ffma2(t00, q0.x, acc[1][0][0]);
                    acc[1][0][1] = ffma2(t00, q1.x, acc[1][0][1]);
                    acc[1][0][2] = ffma2(t00, q2.x, acc[1][0][2]);
                    acc[1][1][0] = ffma2(t01, q0.x, acc[1][1][0]);
                    acc[1][1][1] = ffma2(t01, q1.x, acc[1][1][1]);
                    acc[1][1][2] = ffma2(t01, q2.x, acc[1][1][2]);
                    acc[1][0][0] = ffma2(t10, q0.y, acc[1][0][0]);
                    acc[1][0][1] = ffma2(t10, q1.y, acc[1][0][1]);
                    acc[1][0][2] = ffma2(t10, q2.y, acc[1][0][2]);
                    acc[1][1][0] = ffma2(t11, q0.y, acc[1][1][0]);
                    acc[1][1][1] = ffma2(t11, q1.y, acc[1][1][1]);
                    acc[1][1][2] = ffma2(t11, q2.y, acc[1][1][2]);
                }
            }
        }

        // ---- Phase C: mc = M @ C for both samples, then SGD update ----
        ull mca[2][3] = {{0,0,0},{0,0,0}};
        {
            #pragma unroll 2
            for (int q = 0; q < 16; q++) {
                const float* cqp = Cq + q*36;
                float4 a0 = *(const float4*)(cqp);
                float4 a1 = *(const float4*)(cqp + 4);
                float4 a2 = *(const float4*)(cqp + 8);
                float4 b0 = *(const float4*)(cqp + 16);
                float4 b1 = *(const float4*)(cqp + 20);
                float4 b2 = *(const float4*)(cqp + 24);
                float cA[12] = {a0.x,a0.y,a0.z,a0.w, a1.x,a1.y,a1.z,a1.w, a2.x,a2.y,a2.z,a2.w};
                float cB[12] = {b0.x,b0.y,b0.z,b0.w, b1.x,b1.y,b1.z,b1.w, b2.x,b2.y,b2.z,b2.w};
                #pragma unroll
                for (int i = 0; i < 4; i++) {
                    int kk = 4*q + i;
                    ull pm = *(const ull*)&g_Mp[kk*32 + l];
                    mca[0][0] = ffma2(pm, fdup(cA[i*3+0]), mca[0][0]);
                    mca[0][1] = ffma2(pm, fdup(cA[i*3+1]), mca[0][1]);
                    mca[0][2] = ffma2(pm, fdup(cA[i*3+2]), mca[0][2]);
                    mca[1][0] = ffma2(pm, fdup(cB[i*3+0]), mca[1][0]);
                    mca[1][1] = ffma2(pm, fdup(cB[i*3+1]), mca[1][1]);
                    mca[1][2] = ffma2(pm, fdup(cB[i*3+2]), mca[1][2]);
                }
            }
        }
        __syncwarp();   // all lanes done reading C before update
        #pragma unroll
        for (int s = 0; s < 2; s++)
            #pragma unroll
            for (int k = 0; k < 2; k++) {
                int slot = (qa + (k ? 8 : 0))*36 + s*16 + la3;
                #pragma unroll
                for (int j = 0; j < 3; j++) {
                    float dlo, dhi, m0, m1;
                    funpack(acc[s][k][j], dlo, dhi);    // dlo includes -wv
                    funpack(mca[s][j], m0, m1);
                    float m = k ? m1 : m0;
                    c[s][k][j] -= LRATE * (dlo + dhi + m);
                    Cq[slot + j] = c[s][k][j];
                }
            }
        __syncwarp();
    }

    // ---- output (from registers) ----
    #pragma unroll
    for (int s = 0; s < 2; s++) {
        float* op = out + (size_t)(sA + s) * (KN*3);
        #pragma unroll
        for (int j = 0; j < 3; j++) {
            op[k0*3 + j] = c[s][0][j];
            op[k1*3 + j] = c[s][1][j];
        }
    }
}

extern "C" void kernel_launch(void* const* d_in, const int* in_sizes, int n_in,
                              void* d_out, int out_size)
{
    const float* R_U     = (const float*)d_in[0];
    const float* alpha   = (const float*)d_in[1];
    const float* beta    = (const float*)d_in[2];
    const float* lambdas = (const float*)d_in[3];
    const float* B       = (const float*)d_in[4];
    const float* Bd      = (const float*)d_in[5];
    const float* Bdd     = (const float*)d_in[6];
    const float* Bddd    = (const float*)d_in[7];
    const float* Bpinv   = (const float*)d_in[8];

    cudaFuncSetAttribute(inner_opt_kernel,
                         cudaFuncAttributeMaxDynamicSharedMemorySize, SMEM_BYTES);

    prep_kernel<<<192, 256>>>(B, Bd, Bdd, Bddd, Bpinv, lambdas);
    init_kernel<<<NSAMP/(WARPS*2), 256>>>(R_U, lambdas);
    inner_opt_kernel<<<NSAMP/(WARPS*2), 256, SMEM_BYTES>>>(
        alpha, beta, lambdas, (float*)d_out);
}

// round 13
// speedup vs baseline: 1.2054x; 1.1705x over previous
#include <cuda_runtime.h>
#include <cuda_fp16.h>

typedef unsigned long long ull;

#define HN 512
#define KN 64
#define NSAMP 16384
#define LRATE 0.001f
#define EPSF 1e-8f
#define WARPS 8
#define CHK 64
#define NCHUNK (HN/CHK)
#define FH_H2 68                      // half2 per staged row (272 B); conflict-free

// smem layout (float units)
#define FS_FLOATS   (CHK*FH_H2)       // 4352
#define SC_OFF      FS_FLOATS         // fwd D scratch: [2 samples][64 rows][6] fp32
#define SC_WARP     768
#define CS_OFF      (SC_OFF + WARPS*SC_WARP)
#define CS_WARP     576               // 16 quads * 36 floats (A at +0, B at +16, pad)
#define GB_OFF      (CS_OFF + WARPS*CS_WARP)
#define GB_WARP     768
#define WV_OFF      (GB_OFF + WARPS*GB_WARP)
#define SMEM_FLOATS (WV_OFF + WARPS*384)
#define SMEM_BYTES  (SMEM_FLOATS*4)   // 97280 B -> 2 CTAs/SM

__device__ __align__(16) unsigned g_Fh[HN*KN];        // [h][k] = half2(Bd, Bdd)
__device__ __align__(16) float4 g_PT4[(HN/2)*KN];
__device__ __align__(16) float2 g_Mp[KN*32];
__device__ __align__(16) float  g_CW[(NSAMP/2)*768];

// ---- packed f32x2 helpers ----
__device__ __forceinline__ ull ffma2(ull a, ull b, ull c){
    ull d; asm("fma.rn.f32x2 %0,%1,%2,%3;" : "=l"(d) : "l"(a), "l"(b), "l"(c)); return d;
}
__device__ __forceinline__ void funpack(ull u, float& x, float& y){
    asm("mov.b64 {%0,%1},%2;" : "=f"(x), "=f"(y) : "l"(u));
}
__device__ __forceinline__ ull fdup(float x){
    ull r; asm("mov.b64 %0,{%1,%1};" : "=l"(r) : "f"(x)); return r;
}
__device__ __forceinline__ ull pack2(float lo, float hi){
    ull r; asm("mov.b64 %0,{%1,%2};" : "=l"(r) : "f"(lo), "f"(hi)); return r;
}
__device__ __forceinline__ ull h2f2(unsigned u){
    __half2 h = *(__half2*)&u;
    float2 f = __half22float2(h);
    return pack2(f.x, f.y);
}
__device__ __forceinline__ float rsqrt_fma(float x){
    float y = __uint_as_float(0x5f3759dfu - (__float_as_uint(x) >> 1));
    y = y * (1.5f - 0.5f*x*y*y);
    y = y * (1.5f - 0.5f*x*y*y);
    return y;
}
__device__ __forceinline__ unsigned f2hbits(float x){
    return (unsigned)__half_as_ushort(__float2half_rn(x));
}

#define MMA16816(d, a0, a1, a2, a3, b0, b1) \
    asm volatile("mma.sync.aligned.m16n8k16.row.col.f32.f16.f16.f32 " \
        "{%0,%1,%2,%3}, {%4,%5,%6,%7}, {%8,%9}, {%0,%1,%2,%3};" \
        : "+f"(d[0]), "+f"(d[1]), "+f"(d[2]), "+f"(d[3]) \
        : "r"(a0), "r"(a1), "r"(a2), "r"(a3), "r"(b0), "r"(b1))

// K1: prep (blocks 0..127) + gram (blocks 128..191, ILP accumulators)
__global__ void prep_kernel(const float* __restrict__ B,
                            const float* __restrict__ Bd,
                            const float* __restrict__ Bdd,
                            const float* __restrict__ Bddd,
                            const float* __restrict__ Bpinv,
                            const float* __restrict__ lambdas)
{
    int bid = blockIdx.x, t = threadIdx.x;
    if (bid < 128) {
        int idx = bid*256 + t;
        __half2 hv = __halves2half2(__float2half(Bd[idx]), __float2half(Bdd[idx]));
        g_Fh[idx] = *(unsigned*)&hv;
        if (idx < (HN/2)*KN) {
            int hp = idx >> 6, k = idx & 63;
            int h0 = 2*hp, h1 = 2*hp + 1;
            g_PT4[idx] = make_float4(Bpinv[k*HN + h0], B[h0*KN + k],
                                     Bpinv[k*HN + h1], B[h1*KN + k]);
        }
    } else {
        __shared__ float pab[4][KN], paj[4][KN], Mrow[KN];
        int kk = bid - 128;
        int k2 = t & 63, part = t >> 6;
        float ab0=0.f, ab1=0.f, ab2=0.f, ab3=0.f;
        float aj0=0.f, aj1=0.f, aj2=0.f, aj3=0.f;
        int h0 = part*128;
        #pragma unroll 4
        for (int h = h0; h < h0 + 128; h += 4) {
            ab0 += B[(h+0)*KN + kk]    * B[(h+0)*KN + k2];
            ab1 += B[(h+1)*KN + kk]    * B[(h+1)*KN + k2];
            ab2 += B[(h+2)*KN + kk]    * B[(h+2)*KN + k2];
            ab3 += B[(h+3)*KN + kk]    * B[(h+3)*KN + k2];
            aj0 += Bddd[(h+0)*KN + kk] * Bddd[(h+0)*KN + k2];
            aj1 += Bddd[(h+1)*KN + kk] * Bddd[(h+1)*KN + k2];
            aj2 += Bddd[(h+2)*KN + kk] * Bddd[(h+2)*KN + k2];
            aj3 += Bddd[(h+3)*KN + kk] * Bddd[(h+3)*KN + k2];
        }
        pab[part][k2] = (ab0+ab1) + (ab2+ab3);
        paj[part][k2] = (aj0+aj1) + (aj2+aj3);
        __syncthreads();
        if (t < KN) {
            float sab = pab[0][t]+pab[1][t]+pab[2][t]+pab[3][t];
            float saj = paj[0][t]+paj[1][t]+paj[2][t]+paj[3][t];
            Mrow[t] = 2.f * (lambdas[0]*sab + lambdas[2]*saj);
        }
        __syncthreads();
        if (t < 32) g_Mp[kk*32 + t] = make_float2(Mrow[t], Mrow[t+32]);
    }
}

// K2: init matvecs (unchanged)
__global__ __launch_bounds__(256)
void init_kernel(const float* __restrict__ R_U,
                 const float* __restrict__ lambdas)
{
    const int w = threadIdx.x >> 5;
    const int l = threadIdx.x & 31;
    const int pair = blockIdx.x * WARPS + w;
    const int sA = pair*2, sB = sA + 1;
    const float l1 = lambdas[0];

    ull accw[2][2][3] = {{{0,0,0},{0,0,0}},{{0,0,0},{0,0,0}}};
    const float4* rpA = (const float4*)(R_U + (size_t)sA * (HN*3));
    const float4* rpB = (const float4*)(R_U + (size_t)sB * (HN*3));
    #pragma unroll 1
    for (int q = 0; q < HN/4; q++) {
        ulonglong2 u00 = *(const ulonglong2*)&g_PT4[(2*q  )*KN + l];
        ulonglong2 u01 = *(const ulonglong2*)&g_PT4[(2*q  )*KN + l + 32];
        ulonglong2 u10 = *(const ulonglong2*)&g_PT4[(2*q+1)*KN + l];
        ulonglong2 u11 = *(const ulonglong2*)&g_PT4[(2*q+1)*KN + l + 32];
        #pragma unroll
        for (int s = 0; s < 2; s++) {
            const float4* rp = s ? rpB : rpA;
            float4 r0 = rp[3*q], r1 = rp[3*q+1], r2 = rp[3*q+2];
            float rr[12] = {r0.x,r0.y,r0.z,r0.w, r1.x,r1.y,r1.z,r1.w, r2.x,r2.y,r2.z,r2.w};
            #pragma unroll
            for (int j = 0; j < 3; j++) {
                ull d0 = fdup(rr[j]);
                ull d1 = fdup(rr[3+j]);
                ull d2 = fdup(rr[6+j]);
                ull d3 = fdup(rr[9+j]);
                accw[s][0][j] = ffma2(u00.x, d0, accw[s][0][j]);
                accw[s][0][j] = ffma2(u00.y, d1, accw[s][0][j]);
                accw[s][0][j] = ffma2(u10.x, d2, accw[s][0][j]);
                accw[s][0][j] = ffma2(u10.y, d3, accw[s][0][j]);
                accw[s][1][j] = ffma2(u01.x, d0, accw[s][1][j]);
                accw[s][1][j] = ffma2(u01.y, d1, accw[s][1][j]);
                accw[s][1][j] = ffma2(u11.x, d2, accw[s][1][j]);
                accw[s][1][j] = ffma2(u11.y, d3, accw[s][1][j]);
            }
        }
    }
    float val[24];
    #pragma unroll
    for (int s = 0; s < 2; s++)
        #pragma unroll
        for (int k = 0; k < 2; k++)
            #pragma unroll
            for (int j = 0; j < 3; j++) {
                float cv, wvr;
                funpack(accw[s][k][j], cv, wvr);
                val[s*6 + k*3 + j]      = cv;
                val[12 + s*6 + k*3 + j] = -2.f*l1*wvr;
            }
    float4* cw = (float4*)(g_CW + (size_t)pair*768);
    #pragma unroll
    for (int q = 0; q < 6; q++)
        cw[q*32 + l] = make_float4(val[4*q], val[4*q+1], val[4*q+2], val[4*q+3]);
}

// Elementwise gradient (unchanged)
__device__ __forceinline__ void elemgrad(
    float v0, float v1, float v2,
    float a0, float a1, float a2,
    float aa, float bb, float l2, float* g)
{
    float vsq = v0*v0 + v1*v1 + v2*v2;
    float inv_vn = vsq > 0.f ? rsqrt_fma(vsq) : 0.f;
    float vn  = vsq * inv_vn;
    float vne = vn + EPSF;

    float cx = v1*a2 - v2*a1;
    float cy = v2*a0 - v0*a2;
    float cz = v0*a1 - v1*a0;
    float csq = cx*cx + cy*cy + cz*cz;
    float inv_cn = csq > 0.f ? rsqrtf(csq) : 0.f;
    float cn = csq * inv_cn;

    float inv_den = inv_vn * inv_vn * inv_vn;
    float kappa = cn * inv_den;

    float ks  = fminf(fmaxf(kappa, 1e-4f), 1e4f);
    float lpr = bb * __logf(ks);
    float lp  = fminf(fmaxf(lpr, -10.f), 10.f);
    float traw   = aa * __expf(lp);
    float target = fminf(fmaxf(traw, 1e-6f), 1e6f);

    float u   = vn - target;
    float gvn = 2.f * l2 * u;
    float gt  = (traw > 1e-6f && traw < 1e6f) ? (-2.f * l2 * u) : 0.f;
    float glk = ((lpr > -10.f && lpr < 10.f) ? gt * traw : 0.f) * bb;
    float gk  = (kappa > 1e-4f && kappa < 1e4f) ? glk : 0.f;
    float gcn  = gk * inv_cn;
    float gden = -gk * inv_den;
    gvn += gden * 3.f * vne * vne;

    float scr = gcn * inv_cn;
    float gc0 = scr * cx, gc1 = scr * cy, gc2 = scr * cz;
    float sV = gvn * inv_vn;
    g[0] = sV*v0 + a1*gc2 - a2*gc1;
    g[1] = sV*v1 + a2*gc0 - a0*gc2;
    g[2] = sV*v2 + a0*gc1 - a1*gc0;
    g[3] = gc1*v2 - gc2*v1;
    g[4] = gc2*v0 - gc0*v2;
    g[5] = gc0*v1 - gc1*v0;
}

// K3: main. Forward via m16n8k16 HMMA (A = staged fp16 tile, B built from C);
// backward / Phase C / update unchanged from the proven R10 structure.
__global__ __launch_bounds__(256, 2)
void inner_opt_kernel(const float* __restrict__ alpha,
                      const float* __restrict__ beta,
                      const float* __restrict__ lambdas,
                      float* __restrict__ out)
{
    extern __shared__ __align__(16) float smem[];
    char* Fh = (char*)smem;                                 // [CHK] rows of 272 B
    const int w = threadIdx.x >> 5;
    const int l = threadIdx.x & 31;
    float* ScW = smem + SC_OFF + w*SC_WARP;                 // [2][64][6] fwd D scratch
    float* Cq  = smem + CS_OFF + w*CS_WARP;
    float2* GwA = (float2*)(smem + GB_OFF + w*GB_WARP);
    float2* GwB = GwA + 192;
    float*  Ws  = smem + WV_OFF + w*384;

    const int pair = blockIdx.x * WARPS + w;
    const int sA = pair*2;
    const int sB = sA + 1;
    const int k0 = l, k1 = l + 32;
    const int qa = l >> 2, la3 = (l & 3) * 3;

    const float l2 = lambdas[1];
    const float aaA = alpha[sA], bbA = beta[sA];
    const float aaB = alpha[sB], bbB = beta[sB];

    const unsigned fsh = (unsigned)__cvta_generic_to_shared(Fh);

    float c[2][2][3];

    // ---- load precomputed (c, -wv) ----
    {
        const float4* cw = (const float4*)(g_CW + (size_t)pair*768);
        float val[24];
        #pragma unroll
        for (int q = 0; q < 6; q++) {
            float4 v = cw[q*32 + l];
            val[4*q+0] = v.x; val[4*q+1] = v.y; val[4*q+2] = v.z; val[4*q+3] = v.w;
        }
        #pragma unroll
        for (int s = 0; s < 2; s++)
            #pragma unroll
            for (int k = 0; k < 2; k++) {
                int slot = (qa + (k ? 8 : 0))*36 + s*16 + la3;
                #pragma unroll
                for (int j = 0; j < 3; j++) {
                    float cv = val[s*6 + k*3 + j];
                    c[s][k][j] = cv;
                    Cq[slot + j] = cv;
                    Ws[l*12 + s*6 + k*3 + j] = val[12 + s*6 + k*3 + j];
                }
            }
        __syncwarp();
    }

    // lane constants for fwd B-fragment build
    const int nfb = l >> 2;                        // B fragment column (0..7)
    const bool fb_lo = (nfb < 3);
    const bool fb_hi = (nfb >= 3 && nfb < 6);
    const int fb_j  = fb_lo ? nfb : (fb_hi ? nfb - 3 : 0);
    const int fb_off = (l & 3)*3 + fb_j;           // Cq offset term

    for (int step = 0; step < 3; step++) {
        ull acc[2][2][3];
        #pragma unroll
        for (int s = 0; s < 2; s++)
            #pragma unroll
            for (int k = 0; k < 2; k++)
                #pragma unroll
                for (int j = 0; j < 3; j++)
                    acc[s][k][j] = pack2(Ws[l*12 + s*6 + k*3 + j], 0.f);

        for (int ch = 0; ch < NCHUNK; ch++) {
            const int base = ch * CHK;
            __syncthreads();
            {  // stage fp16 tile (16 KB)
                const float4* src = (const float4*)(g_Fh + base*KN);
                int t = threadIdx.x;
                #pragma unroll
                for (int i = 0; i < 4; i++) {
                    int idx = t + 256*i;
                    int h = idx >> 4, q = idx & 15;
                    *(float4*)(Fh + h*272 + q*16) = src[idx];
                }
            }
            __syncthreads();

            // ---- Phase A (tensor): D[64x8] = Ftile(64x128 fp16) @ Bmat(128x8 fp16) ----
            {
                // build B fragments from fp32 C in smem (per sample, 8 k-tiles)
                unsigned bf[2][8][2];
                #pragma unroll
                for (int kt = 0; kt < 8; kt++)
                    #pragma unroll
                    for (int s = 0; s < 2; s++) {
                        unsigned h0 = f2hbits(Cq[(2*kt  )*36 + s*16 + fb_off]);
                        unsigned h1 = f2hbits(Cq[(2*kt+1)*36 + s*16 + fb_off]);
                        bf[s][kt][0] = fb_lo ? h0 : (fb_hi ? (h0 << 16) : 0u);
                        bf[s][kt][1] = fb_lo ? h1 : (fb_hi ? (h1 << 16) : 0u);
                    }

                #pragma unroll
                for (int mt = 0; mt < 4; mt++) {
                    float dA[4] = {0.f,0.f,0.f,0.f};
                    float dB[4] = {0.f,0.f,0.f,0.f};
                    unsigned arow = fsh + (unsigned)((16*mt + (l & 15))*272 + (l >> 4)*16);
                    #pragma unroll
                    for (int kt = 0; kt < 8; kt++) {
                        unsigned a0, a1, a2, a3;
                        asm volatile(
                            "ldmatrix.sync.aligned.m8n8.x4.shared.b16 {%0,%1,%2,%3}, [%4];"
                            : "=r"(a0), "=r"(a1), "=r"(a2), "=r"(a3)
                            : "r"(arow + (unsigned)(kt*32)));
                        MMA16816(dA, a0, a1, a2, a3, bf[0][kt][0], bf[0][kt][1]);
                        MMA16816(dB, a0, a1, a2, a3, bf[1][kt][0], bf[1][kt][1]);
                    }
                    if ((l & 3) < 3) {
                        int r0 = 16*mt + (l >> 2);
                        int cc = 2*(l & 3);
                        *(float2*)(ScW + r0*6 + cc)         = make_float2(dA[0], dA[1]);
                        *(float2*)(ScW + (r0+8)*6 + cc)     = make_float2(dA[2], dA[3]);
                        *(float2*)(ScW + 384 + r0*6 + cc)     = make_float2(dB[0], dB[1]);
                        *(float2*)(ScW + 384 + (r0+8)*6 + cc) = make_float2(dB[2], dB[3]);
                    }
                }
                __syncwarp();

                // gather V,A + elementwise grads -> Gw (layout unchanged)
                float g[6];
                #pragma unroll
                for (int s = 0; s < 2; s++) {
                    float2* Gw = s ? GwB : GwA;
                    float aa = s ? aaB : aaA;
                    float bb = s ? bbB : bbA;
                    const float* sc = ScW + s*384;
                    #pragma unroll
                    for (int r = 0; r < 2; r++) {
                        int hh = l + 32*r;
                        float2 p0 = *(const float2*)(sc + hh*6 + 0);
                        float2 p1 = *(const float2*)(sc + hh*6 + 2);
                        float2 p2 = *(const float2*)(sc + hh*6 + 4);
                        elemgrad(p0.x, p0.y, p1.x, p1.y, p2.x, p2.y, aa, bb, l2, g);
                        #pragma unroll
                        for (int j = 0; j < 3; j++)
                            Gw[j*CHK + hh] = make_float2(g[j], g[3+j]);
                    }
                }
            }
            __syncwarp();

            // ---- Phase B: dC accumulation (unchanged scalar fp16-column path) ----
            {
                const ulonglong2* pgA0 = (const ulonglong2*)(GwA);
                const ulonglong2* pgA1 = (const ulonglong2*)(GwA + CHK);
                const ulonglong2* pgA2 = (const ulonglong2*)(GwA + 2*CHK);
                const ulonglong2* pgB0 = (const ulonglong2*)(GwB);
                const ulonglong2* pgB1 = (const ulonglong2*)(GwB + CHK);
                const ulonglong2* pgB2 = (const ulonglong2*)(GwB + 2*CHK);
                #pragma unroll 2
                for (int hp = 0; hp < 32; hp++) {
                    const char* rowA = Fh + (2*hp)*272;
                    const char* rowB = Fh + (2*hp+1)*272;
                    ull t00 = h2f2(*(const unsigned*)(rowA + l*4));
                    ull t01 = h2f2(*(const unsigned*)(rowA + (l+32)*4));
                    ull t10 = h2f2(*(const unsigned*)(rowB + l*4));
                    ull t11 = h2f2(*(const unsigned*)(rowB + (l+32)*4));
                    ulonglong2 p0 = pgA0[hp], p1 = pgA1[hp], p2 = pgA2[hp];
                    acc[0][0][0] = ffma2(t00, p0.x, acc[0][0][0]);
                    acc[0][0][1] = ffma2(t00, p1.x, acc[0][0][1]);
                    acc[0][0][2] = ffma2(t00, p2.x, acc[0][0][2]);
                    acc[0][1][0] = ffma2(t01, p0.x, acc[0][1][0]);
                    acc[0][1][1] = ffma2(t01, p1.x, acc[0][1][1]);
                    acc[0][1][2] = ffma2(t01, p2.x, acc[0][1][2]);
                    acc[0][0][0] = ffma2(t10, p0.y, acc[0][0][0]);
                    acc[0][0][1] = ffma2(t10, p1.y, acc[0][0][1]);
                    acc[0][0][2] = ffma2(t10, p2.y, acc[0][0][2]);
                    acc[0][1][0] = ffma2(t11, p0.y, acc[0][1][0]);
                    acc[0][1][1] = ffma2(t11, p1.y, acc[0][1][1]);
                    acc[0][1][2] = ffma2(t11, p2.y, acc[0][1][2]);
                    ulonglong2 q0 = pgB0[hp], q1 = pgB1[hp], q2 = pgB2[hp];
                    acc[1][0][0] = ffma2(t00, q0.x, acc[1][0][0]);
                    acc[1][0][1] = ffma2(t00, q1.x, acc[1][0][1]);
                    acc[1][0][2] = ffma2(t00, q2.x, acc[1][0][2]);
                    acc[1][1][0] = ffma2(t01, q0.x, acc[1][1][0]);
                    acc[1][1][1] = ffma2(t01, q1.x, acc[1][1][1]);
                    acc[1][1][2] = ffma2(t01, q2.x, acc[1][1][2]);
                    acc[1][0][0] = ffma2(t10, q0.y, acc[1][0][0]);
                    acc[1][0][1] = ffma2(t10, q1.y, acc[1][0][1]);
                    acc[1][0][2] = ffma2(t10, q2.y, acc[1][0][2]);
                    acc[1][1][0] = ffma2(t11, q0.y, acc[1][1][0]);
                    acc[1][1][1] = ffma2(t11, q1.y, acc[1][1][1]);
                    acc[1][1][2] = ffma2(t11, q2.y, acc[1][1][2]);
                }
            }
        }

        // ---- Phase C: mc = M @ C (unchanged) ----
        ull mca[2][3] = {{0,0,0},{0,0,0}};
        {
            #pragma unroll 2
            for (int q = 0; q < 16; q++) {
                const float* cqp = Cq + q*36;
                float4 a0 = *(const float4*)(cqp);
                float4 a1 = *(const float4*)(cqp + 4);
                float4 a2 = *(const float4*)(cqp + 8);
                float4 b0 = *(const float4*)(cqp + 16);
                float4 b1 = *(const float4*)(cqp + 20);
                float4 b2 = *(const float4*)(cqp + 24);
                float cA[12] = {a0.x,a0.y,a0.z,a0.w, a1.x,a1.y,a1.z,a1.w, a2.x,a2.y,a2.z,a2.w};
                float cB[12] = {b0.x,b0.y,b0.z,b0.w, b1.x,b1.y,b1.z,b1.w, b2.x,b2.y,b2.z,b2.w};
                #pragma unroll
                for (int i = 0; i < 4; i++) {
                    int kk = 4*q + i;
                    ull pm = *(const ull*)&g_Mp[kk*32 + l];
                    mca[0][0] = ffma2(pm, fdup(cA[i*3+0]), mca[0][0]);
                    mca[0][1] = ffma2(pm, fdup(cA[i*3+1]), mca[0][1]);
                    mca[0][2] = ffma2(pm, fdup(cA[i*3+2]), mca[0][2]);
                    mca[1][0] = ffma2(pm, fdup(cB[i*3+0]), mca[1][0]);
                    mca[1][1] = ffma2(pm, fdup(cB[i*3+1]), mca[1][1]);
                    mca[1][2] = ffma2(pm, fdup(cB[i*3+2]), mca[1][2]);
                }
            }
        }
        __syncwarp();
        #pragma unroll
        for (int s = 0; s < 2; s++)
            #pragma unroll
            for (int k = 0; k < 2; k++) {
                int slot = (qa + (k ? 8 : 0))*36 + s*16 + la3;
                #pragma unroll
                for (int j = 0; j < 3; j++) {
                    float dlo, dhi, m0, m1;
                    funpack(acc[s][k][j], dlo, dhi);
                    funpack(mca[s][j], m0, m1);
                    float m = k ? m1 : m0;
                    c[s][k][j] -= LRATE * (dlo + dhi + m);
                    Cq[slot + j] = c[s][k][j];
                }
            }
        __syncwarp();
    }

    // ---- output ----
    #pragma unroll
    for (int s = 0; s < 2; s++) {
        float* op = out + (size_t)(sA + s) * (KN*3);
        #pragma unroll
        for (int j = 0; j < 3; j++) {
            op[k0*3 + j] = c[s][0][j];
            op[k1*3 + j] = c[s][1][j];
        }
    }
}

extern "C" void kernel_launch(void* const* d_in, const int* in_sizes, int n_in,
                              void* d_out, int out_size)
{
    const float* R_U     = (const float*)d_in[0];
    const float* alpha   = (const float*)d_in[1];
    const float* beta    = (const float*)d_in[2];
    const float* lambdas = (const float*)d_in[3];
    const float* B       = (const float*)d_in[4];
    const float* Bd      = (const float*)d_in[5];
    const float* Bdd     = (const float*)d_in[6];
    const float* Bddd    = (const float*)d_in[7];
    const float* Bpinv   = (const float*)d_in[8];

    cudaFuncSetAttribute(inner_opt_kernel,
                         cudaFuncAttributeMaxDynamicSharedMemorySize, SMEM_BYTES);

    prep_kernel<<<192, 256>>>(B, Bd, Bdd, Bddd, Bpinv, lambdas);
    init_kernel<<<NSAMP/(WARPS*2), 256>>>(R_U, lambdas);
    inner_opt_kernel<<<NSAMP/(WARPS*2), 256, SMEM_BYTES>>>(
        alpha, beta, lambdas, (float*)d_out);
}

// round 14
// speedup vs baseline: 1.7868x; 1.4823x over previous
#include <cuda_runtime.h>
#include <cuda_fp16.h>

typedef unsigned long long ull;

#define HN 512
#define KN 64
#define NSAMP 16384
#define LRATE 0.001f
#define EPSF 1e-8f
#define WARPS 8
#define CHK 64
#define NCHUNK (HN/CHK)
#define FH_H2 68                      // half2 per staged row (272 B)
#define GSCALE 0.00390625f            // 2^-8 G scaling for fp16 range
#define GBACK  256.0f

// smem layout (float units)
#define FS_FLOATS   (CHK*FH_H2)       // 4352
#define SC_OFF      FS_FLOATS         // scratch: [2][64][6] fwd / [128][6] bwd extraction
#define SC_WARP     768
#define CS_OFF      (SC_OFF + WARPS*SC_WARP)
#define CS_WARP     576               // 16 quads * 36 floats (A @+0, B @+16)
#define GB_OFF      (CS_OFF + WARPS*CS_WARP)
#define GB_WARP     768               // W: 2 samples x 32 rows x 9 words (576 used)
#define WV_OFF      (GB_OFF + WARPS*GB_WARP)
#define SMEM_FLOATS (WV_OFF + WARPS*384)
#define SMEM_BYTES  (SMEM_FLOATS*4)   // 97280 B -> 2 CTAs/SM

__device__ __align__(16) unsigned g_Fh[HN*KN];        // [h][k] = half2(Bd, Bdd)
__device__ __align__(16) float4 g_PT4[(HN/2)*KN];
__device__ __align__(16) float2 g_Mp[KN*32];
__device__ __align__(16) float  g_CW[(NSAMP/2)*768];

// ---- helpers ----
__device__ __forceinline__ ull ffma2(ull a, ull b, ull c){
    ull d; asm("fma.rn.f32x2 %0,%1,%2,%3;" : "=l"(d) : "l"(a), "l"(b), "l"(c)); return d;
}
__device__ __forceinline__ void funpack(ull u, float& x, float& y){
    asm("mov.b64 {%0,%1},%2;" : "=f"(x), "=f"(y) : "l"(u));
}
__device__ __forceinline__ ull fdup(float x){
    ull r; asm("mov.b64 %0,{%1,%1};" : "=l"(r) : "f"(x)); return r;
}
__device__ __forceinline__ float rsqrt_fma(float x){
    float y = __uint_as_float(0x5f3759dfu - (__float_as_uint(x) >> 1));
    y = y * (1.5f - 0.5f*x*y*y);
    y = y * (1.5f - 0.5f*x*y*y);
    return y;
}
__device__ __forceinline__ unsigned f2hbits(float x){
    return (unsigned)__half_as_ushort(__float2half_rn(x));
}
__device__ __forceinline__ unsigned packg(float lo, float hi){
    float a = fminf(fmaxf(lo*GSCALE, -60000.f), 60000.f);
    float b = fminf(fmaxf(hi*GSCALE, -60000.f), 60000.f);
    return f2hbits(a) | (f2hbits(b) << 16);
}

#define MMA16816(d, a0, a1, a2, a3, b0, b1) \
    asm volatile("mma.sync.aligned.m16n8k16.row.col.f32.f16.f16.f32 " \
        "{%0,%1,%2,%3}, {%4,%5,%6,%7}, {%8,%9}, {%0,%1,%2,%3};" \
        : "+f"(d[0]), "+f"(d[1]), "+f"(d[2]), "+f"(d[3]) \
        : "r"(a0), "r"(a1), "r"(a2), "r"(a3), "r"(b0), "r"(b1))

#define LDSM4(a0,a1,a2,a3,addr) \
    asm volatile("ldmatrix.sync.aligned.m8n8.x4.shared.b16 {%0,%1,%2,%3}, [%4];" \
        : "=r"(a0),"=r"(a1),"=r"(a2),"=r"(a3) : "r"(addr))

#define LDSM4T(a0,a1,a2,a3,addr) \
    asm volatile("ldmatrix.sync.aligned.m8n8.x4.trans.shared.b16 {%0,%1,%2,%3}, [%4];" \
        : "=r"(a0),"=r"(a1),"=r"(a2),"=r"(a3) : "r"(addr))

// K1: prep + gram (unchanged, proven)
__global__ void prep_kernel(const float* __restrict__ B,
                            const float* __restrict__ Bd,
                            const float* __restrict__ Bdd,
                            const float* __restrict__ Bddd,
                            const float* __restrict__ Bpinv,
                            const float* __restrict__ lambdas)
{
    int bid = blockIdx.x, t = threadIdx.x;
    if (bid < 128) {
        int idx = bid*256 + t;
        __half2 hv = __halves2half2(__float2half(Bd[idx]), __float2half(Bdd[idx]));
        g_Fh[idx] = *(unsigned*)&hv;
        if (idx < (HN/2)*KN) {
            int hp = idx >> 6, k = idx & 63;
            int h0 = 2*hp, h1 = 2*hp + 1;
            g_PT4[idx] = make_float4(Bpinv[k*HN + h0], B[h0*KN + k],
                                     Bpinv[k*HN + h1], B[h1*KN + k]);
        }
    } else {
        __shared__ float pab[4][KN], paj[4][KN], Mrow[KN];
        int kk = bid - 128;
        int k2 = t & 63, part = t >> 6;
        float ab0=0.f, ab1=0.f, ab2=0.f, ab3=0.f;
        float aj0=0.f, aj1=0.f, aj2=0.f, aj3=0.f;
        int h0 = part*128;
        #pragma unroll 4
        for (int h = h0; h < h0 + 128; h += 4) {
            ab0 += B[(h+0)*KN + kk]    * B[(h+0)*KN + k2];
            ab1 += B[(h+1)*KN + kk]    * B[(h+1)*KN + k2];
            ab2 += B[(h+2)*KN + kk]    * B[(h+2)*KN + k2];
            ab3 += B[(h+3)*KN + kk]    * B[(h+3)*KN + k2];
            aj0 += Bddd[(h+0)*KN + kk] * Bddd[(h+0)*KN + k2];
            aj1 += Bddd[(h+1)*KN + kk] * Bddd[(h+1)*KN + k2];
            aj2 += Bddd[(h+2)*KN + kk] * Bddd[(h+2)*KN + k2];
            aj3 += Bddd[(h+3)*KN + kk] * Bddd[(h+3)*KN + k2];
        }
        pab[part][k2] = (ab0+ab1) + (ab2+ab3);
        paj[part][k2] = (aj0+aj1) + (aj2+aj3);
        __syncthreads();
        if (t < KN) {
            float sab = pab[0][t]+pab[1][t]+pab[2][t]+pab[3][t];
            float saj = paj[0][t]+paj[1][t]+paj[2][t]+paj[3][t];
            Mrow[t] = 2.f * (lambdas[0]*sab + lambdas[2]*saj);
        }
        __syncthreads();
        if (t < 32) g_Mp[kk*32 + t] = make_float2(Mrow[t], Mrow[t+32]);
    }
}

// K2: init matvecs (unchanged, proven)
__global__ __launch_bounds__(256)
void init_kernel(const float* __restrict__ R_U,
                 const float* __restrict__ lambdas)
{
    const int w = threadIdx.x >> 5;
    const int l = threadIdx.x & 31;
    const int pair = blockIdx.x * WARPS + w;
    const int sA = pair*2, sB = sA + 1;
    const float l1 = lambdas[0];

    ull accw[2][2][3] = {{{0,0,0},{0,0,0}},{{0,0,0},{0,0,0}}};
    const float4* rpA = (const float4*)(R_U + (size_t)sA * (HN*3));
    const float4* rpB = (const float4*)(R_U + (size_t)sB * (HN*3));
    #pragma unroll 1
    for (int q = 0; q < HN/4; q++) {
        ulonglong2 u00 = *(const ulonglong2*)&g_PT4[(2*q  )*KN + l];
        ulonglong2 u01 = *(const ulonglong2*)&g_PT4[(2*q  )*KN + l + 32];
        ulonglong2 u10 = *(const ulonglong2*)&g_PT4[(2*q+1)*KN + l];
        ulonglong2 u11 = *(const ulonglong2*)&g_PT4[(2*q+1)*KN + l + 32];
        #pragma unroll
        for (int s = 0; s < 2; s++) {
            const float4* rp = s ? rpB : rpA;
            float4 r0 = rp[3*q], r1 = rp[3*q+1], r2 = rp[3*q+2];
            float rr[12] = {r0.x,r0.y,r0.z,r0.w, r1.x,r1.y,r1.z,r1.w, r2.x,r2.y,r2.z,r2.w};
            #pragma unroll
            for (int j = 0; j < 3; j++) {
                ull d0 = fdup(rr[j]);
                ull d1 = fdup(rr[3+j]);
                ull d2 = fdup(rr[6+j]);
                ull d3 = fdup(rr[9+j]);
                accw[s][0][j] = ffma2(u00.x, d0, accw[s][0][j]);
                accw[s][0][j] = ffma2(u00.y, d1, accw[s][0][j]);
                accw[s][0][j] = ffma2(u10.x, d2, accw[s][0][j]);
                accw[s][0][j] = ffma2(u10.y, d3, accw[s][0][j]);
                accw[s][1][j] = ffma2(u01.x, d0, accw[s][1][j]);
                accw[s][1][j] = ffma2(u01.y, d1, accw[s][1][j]);
                accw[s][1][j] = ffma2(u11.x, d2, accw[s][1][j]);
                accw[s][1][j] = ffma2(u11.y, d3, accw[s][1][j]);
            }
        }
    }
    float val[24];
    #pragma unroll
    for (int s = 0; s < 2; s++)
        #pragma unroll
        for (int k = 0; k < 2; k++)
            #pragma unroll
            for (int j = 0; j < 3; j++) {
                float cv, wvr;
                funpack(accw[s][k][j], cv, wvr);
                val[s*6 + k*3 + j]      = cv;
                val[12 + s*6 + k*3 + j] = -2.f*l1*wvr;
            }
    float4* cw = (float4*)(g_CW + (size_t)pair*768);
    #pragma unroll
    for (int q = 0; q < 6; q++)
        cw[q*32 + l] = make_float4(val[4*q], val[4*q+1], val[4*q+2], val[4*q+3]);
}

// Elementwise gradient (unchanged)
__device__ __forceinline__ void elemgrad(
    float v0, float v1, float v2,
    float a0, float a1, float a2,
    float aa, float bb, float l2, float* g)
{
    float vsq = v0*v0 + v1*v1 + v2*v2;
    float inv_vn = vsq > 0.f ? rsqrt_fma(vsq) : 0.f;
    float vn  = vsq * inv_vn;
    float vne = vn + EPSF;

    float cx = v1*a2 - v2*a1;
    float cy = v2*a0 - v0*a2;
    float cz = v0*a1 - v1*a0;
    float csq = cx*cx + cy*cy + cz*cz;
    float inv_cn = csq > 0.f ? rsqrtf(csq) : 0.f;
    float cn = csq * inv_cn;

    float inv_den = inv_vn * inv_vn * inv_vn;
    float kappa = cn * inv_den;

    float ks  = fminf(fmaxf(kappa, 1e-4f), 1e4f);
    float lpr = bb * __logf(ks);
    float lp  = fminf(fmaxf(lpr, -10.f), 10.f);
    float traw   = aa * __expf(lp);
    float target = fminf(fmaxf(traw, 1e-6f), 1e6f);

    float u   = vn - target;
    float gvn = 2.f * l2 * u;
    float gt  = (traw > 1e-6f && traw < 1e6f) ? (-2.f * l2 * u) : 0.f;
    float glk = ((lpr > -10.f && lpr < 10.f) ? gt * traw : 0.f) * bb;
    float gk  = (kappa > 1e-4f && kappa < 1e4f) ? glk : 0.f;
    float gcn  = gk * inv_cn;
    float gden = -gk * inv_den;
    gvn += gden * 3.f * vne * vne;

    float scr = gcn * inv_cn;
    float gc0 = scr * cx, gc1 = scr * cy, gc2 = scr * cz;
    float sV = gvn * inv_vn;
    g[0] = sV*v0 + a1*gc2 - a2*gc1;
    g[1] = sV*v1 + a2*gc0 - a0*gc2;
    g[2] = sV*v2 + a0*gc1 - a1*gc0;
    g[3] = gc1*v2 - gc2*v1;
    g[4] = gc2*v0 - gc0*v2;
    g[5] = gc0*v1 - gc1*v0;
}

// K3: main. Forward AND backward on HMMA; backward D accumulated in mma regs
// across chunks. dC[k][j] = D[2k][j] + D[2k+1][3+j] (F tile interleaving trick).
__global__ __launch_bounds__(256, 2)
void inner_opt_kernel(const float* __restrict__ alpha,
                      const float* __restrict__ beta,
                      const float* __restrict__ lambdas,
                      float* __restrict__ out)
{
    extern __shared__ __align__(16) float smem[];
    char* Fh = (char*)smem;                                 // [CHK] rows of 272 B
    const int w = threadIdx.x >> 5;
    const int l = threadIdx.x & 31;
    float* ScW = smem + SC_OFF + w*SC_WARP;                 // scratch
    float* Cq  = smem + CS_OFF + w*CS_WARP;
    unsigned* Wp = (unsigned*)(smem + GB_OFF + w*GB_WARP);  // G' fp16 words, [2][32][9]
    float*  Ws  = smem + WV_OFF + w*384;                    // -wv stash

    const int pair = blockIdx.x * WARPS + w;
    const int sA = pair*2;
    const int sB = sA + 1;
    const int k0 = l, k1 = l + 32;
    const int qa = l >> 2, la3 = (l & 3) * 3;

    const float l2 = lambdas[1];
    const float aaA = alpha[sA], bbA = beta[sA];
    const float aaB = alpha[sB], bbB = beta[sB];

    const unsigned fsh = (unsigned)__cvta_generic_to_shared(Fh);

    // ---- load precomputed (c, -wv) ----
    {
        const float4* cw = (const float4*)(g_CW + (size_t)pair*768);
        float val[24];
        #pragma unroll
        for (int q = 0; q < 6; q++) {
            float4 v = cw[q*32 + l];
            val[4*q+0] = v.x; val[4*q+1] = v.y; val[4*q+2] = v.z; val[4*q+3] = v.w;
        }
        #pragma unroll
        for (int s = 0; s < 2; s++)
            #pragma unroll
            for (int k = 0; k < 2; k++) {
                int slot = (qa + (k ? 8 : 0))*36 + s*16 + la3;
                #pragma unroll
                for (int j = 0; j < 3; j++) {
                    Cq[slot + j] = val[s*6 + k*3 + j];
                    Ws[l*12 + s*6 + k*3 + j] = val[12 + s*6 + k*3 + j];
                }
            }
        __syncwarp();
    }

    // lane constants: fwd B-frag build
    const int nfb = l >> 2;
    const bool fb_lo = (nfb < 3);
    const bool fb_hi = (nfb >= 3 && nfb < 6);
    const int fb_j  = fb_lo ? nfb : (fb_hi ? nfb - 3 : 0);
    const int fb_off = (l & 3)*3 + fb_j;
    // lane constants: bwd ldmatrix.trans base offset
    const unsigned bwd_off = (unsigned)(((l & 7) + ((l & 16) ? 8 : 0))*272
                                        + ((l & 8) ? 8 : 0)*2);
    // lane constants: bwd B-frag word indices
    const int wb0 = (l & 3)*9 + (l >> 2);
    const int wb1 = ((l & 3) + 4)*9 + (l >> 2);

    for (int step = 0; step < 3; step++) {
        float accD[2][8][4];   // bwd D accumulators, persist across chunks
        #pragma unroll
        for (int s = 0; s < 2; s++)
            #pragma unroll
            for (int mt = 0; mt < 8; mt++)
                #pragma unroll
                for (int e = 0; e < 4; e++)
                    accD[s][mt][e] = 0.f;

        for (int ch = 0; ch < NCHUNK; ch++) {
            const int base = ch * CHK;
            __syncthreads();
            {  // stage fp16 tile (16 KB)
                const float4* src = (const float4*)(g_Fh + base*KN);
                int t = threadIdx.x;
                #pragma unroll
                for (int i = 0; i < 4; i++) {
                    int idx = t + 256*i;
                    int h = idx >> 4, q = idx & 15;
                    *(float4*)(Fh + h*272 + q*16) = src[idx];
                }
            }
            __syncthreads();

            // ---- Phase A (tensor fwd): D[64x8] = Ftile @ Bmat(C) ----
            {
                unsigned bf[2][8][2];
                #pragma unroll
                for (int kt = 0; kt < 8; kt++)
                    #pragma unroll
                    for (int s = 0; s < 2; s++) {
                        unsigned h0 = f2hbits(Cq[(2*kt  )*36 + s*16 + fb_off]);
                        unsigned h1 = f2hbits(Cq[(2*kt+1)*36 + s*16 + fb_off]);
                        bf[s][kt][0] = fb_lo ? h0 : (fb_hi ? (h0 << 16) : 0u);
                        bf[s][kt][1] = fb_lo ? h1 : (fb_hi ? (h1 << 16) : 0u);
                    }
                #pragma unroll
                for (int mt = 0; mt < 4; mt++) {
                    float dA[4] = {0.f,0.f,0.f,0.f};
                    float dB[4] = {0.f,0.f,0.f,0.f};
                    unsigned arow = fsh + (unsigned)((16*mt + (l & 15))*272 + (l >> 4)*16);
                    #pragma unroll
                    for (int kt = 0; kt < 8; kt++) {
                        unsigned a0, a1, a2, a3;
                        LDSM4(a0, a1, a2, a3, arow + (unsigned)(kt*32));
                        MMA16816(dA, a0, a1, a2, a3, bf[0][kt][0], bf[0][kt][1]);
                        MMA16816(dB, a0, a1, a2, a3, bf[1][kt][0], bf[1][kt][1]);
                    }
                    if ((l & 3) < 3) {
                        int r0 = 16*mt + (l >> 2);
                        int cc = 2*(l & 3);
                        *(float2*)(ScW + r0*6 + cc)           = make_float2(dA[0], dA[1]);
                        *(float2*)(ScW + (r0+8)*6 + cc)       = make_float2(dA[2], dA[3]);
                        *(float2*)(ScW + 384 + r0*6 + cc)     = make_float2(dB[0], dB[1]);
                        *(float2*)(ScW + 384 + (r0+8)*6 + cc) = make_float2(dB[2], dB[3]);
                    }
                }
                __syncwarp();

                // gather rows 2l, 2l+1 -> elemgrad -> packed fp16 G' words
                float g0[6], g1[6];
                #pragma unroll
                for (int s = 0; s < 2; s++) {
                    const float* sc = ScW + s*384;
                    unsigned* wp = Wp + s*288;
                    float aa = s ? aaB : aaA;
                    float bb = s ? bbB : bbA;
                    float4 qaV = *(const float4*)(sc + 12*l);
                    float2 qbV = *(const float2*)(sc + 12*l + 4);
                    elemgrad(qaV.x, qaV.y, qaV.z, qaV.w, qbV.x, qbV.y, aa, bb, l2, g0);
                    float2 qcV = *(const float2*)(sc + 12*l + 6);
                    float4 qdV = *(const float4*)(sc + 12*l + 8);
                    elemgrad(qcV.x, qcV.y, qdV.x, qdV.y, qdV.z, qdV.w, aa, bb, l2, g1);
                    #pragma unroll
                    for (int n = 0; n < 6; n++)
                        wp[l*9 + n] = packg(g0[n], g1[n]);
                    wp[l*9 + 6] = 0u;
                    wp[l*9 + 7] = 0u;
                }
            }
            __syncwarp();

            // ---- Phase B (tensor bwd): accD += Ftile^T @ G' ----
            {
                #pragma unroll
                for (int kt = 0; kt < 4; kt++) {
                    unsigned bA0 = Wp[8*kt*9 + wb0];
                    unsigned bA1 = Wp[8*kt*9 + wb1];
                    unsigned bB0 = Wp[288 + 8*kt*9 + wb0];
                    unsigned bB1 = Wp[288 + 8*kt*9 + wb1];
                    unsigned abase = fsh + bwd_off + (unsigned)(16*kt*272);
                    #pragma unroll
                    for (int mt = 0; mt < 8; mt++) {
                        unsigned a0, a1, a2, a3;
                        LDSM4T(a0, a1, a2, a3, abase + (unsigned)(mt*32));
                        MMA16816(accD[0][mt], a0, a1, a2, a3, bA0, bA1);
                        MMA16816(accD[1][mt], a0, a1, a2, a3, bB0, bB1);
                    }
                }
            }
            __syncwarp();
        }

        // ---- Phase C: mc = M @ C ----
        ull mca[2][3] = {{0,0,0},{0,0,0}};
        {
            #pragma unroll 2
            for (int q = 0; q < 16; q++) {
                const float* cqp = Cq + q*36;
                float4 a0 = *(const float4*)(cqp);
                float4 a1 = *(const float4*)(cqp + 4);
                float4 a2 = *(const float4*)(cqp + 8);
                float4 b0 = *(const float4*)(cqp + 16);
                float4 b1 = *(const float4*)(cqp + 20);
                float4 b2 = *(const float4*)(cqp + 24);
                float cA[12] = {a0.x,a0.y,a0.z,a0.w, a1.x,a1.y,a1.z,a1.w, a2.x,a2.y,a2.z,a2.w};
                float cB[12] = {b0.x,b0.y,b0.z,b0.w, b1.x,b1.y,b1.z,b1.w, b2.x,b2.y,b2.z,b2.w};
                #pragma unroll
                for (int i = 0; i < 4; i++) {
                    int kk = 4*q + i;
                    ull pm = *(const ull*)&g_Mp[kk*32 + l];
                    mca[0][0] = ffma2(pm, fdup(cA[i*3+0]), mca[0][0]);
                    mca[0][1] = ffma2(pm, fdup(cA[i*3+1]), mca[0][1]);
                    mca[0][2] = ffma2(pm, fdup(cA[i*3+2]), mca[0][2]);
                    mca[1][0] = ffma2(pm, fdup(cB[i*3+0]), mca[1][0]);
                    mca[1][1] = ffma2(pm, fdup(cB[i*3+1]), mca[1][1]);
                    mca[1][2] = ffma2(pm, fdup(cB[i*3+2]), mca[1][2]);
                }
            }
        }
        __syncwarp();

        // ---- per sample: extract D, combine, SGD update ----
        #pragma unroll
        for (int s = 0; s < 2; s++) {
            // dump D (rescaled) to ScW as [128][6]
            #pragma unroll
            for (int mt = 0; mt < 8; mt++) {
                if ((l & 3) < 3) {
                    int r0 = 16*mt + (l >> 2);
                    int n2 = 2*(l & 3);
                    *(float2*)(ScW + r0*6 + n2) =
                        make_float2(accD[s][mt][0]*GBACK, accD[s][mt][1]*GBACK);
                    *(float2*)(ScW + (r0+8)*6 + n2) =
                        make_float2(accD[s][mt][2]*GBACK, accD[s][mt][3]*GBACK);
                }
            }
            __syncwarp();
            float m0f, m1f;
            #pragma unroll
            for (int k = 0; k < 2; k++) {
                int kk = k ? k1 : k0;
                int slot = (qa + (k ? 8 : 0))*36 + s*16 + la3;
                #pragma unroll
                for (int j = 0; j < 3; j++) {
                    float dval = ScW[(2*kk)*6 + j] + ScW[(2*kk+1)*6 + 3 + j];
                    funpack(mca[s][j], m0f, m1f);
                    float m = k ? m1f : m0f;
                    float negwv = Ws[l*12 + s*6 + k*3 + j];
                    Cq[slot + j] = Cq[slot + j] - LRATE * (dval + m + negwv);
                }
            }
            __syncwarp();
        }
    }

    // ---- output (from Cq) ----
    #pragma unroll
    for (int s = 0; s < 2; s++) {
        float* op = out + (size_t)(sA + s) * (KN*3);
        #pragma unroll
        for (int k = 0; k < 2; k++) {
            int kk = k ? k1 : k0;
            int slot = (qa + (k ? 8 : 0))*36 + s*16 + la3;
            #pragma unroll
            for (int j = 0; j < 3; j++)
                op[kk*3 + j] = Cq[slot + j];
        }
    }
}

extern "C" void kernel_launch(void* const* d_in, const int* in_sizes, int n_in,
                              void* d_out, int out_size)
{
    const float* R_U     = (const float*)d_in[0];
    const float* alpha   = (const float*)d_in[1];
    const float* beta    = (const float*)d_in[2];
    const float* lambdas = (const float*)d_in[3];
    const float* B       = (const float*)d_in[4];
    const float* Bd      = (const float*)d_in[5];
    const float* Bdd     = (const float*)d_in[6];
    const float* Bddd    = (const float*)d_in[7];
    const float* Bpinv   = (const float*)d_in[8];

    cudaFuncSetAttribute(inner_opt_kernel,
                         cudaFuncAttributeMaxDynamicSharedMemorySize, SMEM_BYTES);

    prep_kernel<<<192, 256>>>(B, Bd, Bdd, Bddd, Bpinv, lambdas);
    init_kernel<<<NSAMP/(WARPS*2), 256>>>(R_U, lambdas);
    inner_opt_kernel<<<NSAMP/(WARPS*2), 256, SMEM_BYTES>>>(
        alpha, beta, lambdas, (float*)d_out);
}

// round 15
// speedup vs baseline: 1.8559x; 1.0387x over previous
#include <cuda_runtime.h>
#include <cuda_fp16.h>

typedef unsigned long long ull;

#define HN 512
#define KN 64
#define NSAMP 16384
#define LRATE 0.001f
#define EPSF 1e-8f
#define WARPS 8
#define CHK 64
#define NCHUNK (HN/CHK)
#define FH_H2 68                      // half2 per staged row (272 B)
#define FBUF_B (CHK*272)              // 17408 B per F buffer
#define GSCALE 0.00390625f            // 2^-8 G scaling for fp16 range
#define GBACK  256.0f

// smem layout (float units)
#define FS_FLOATS   (2*CHK*FH_H2)     // 8704 (double-buffered fp16 F)
#define SC_OFF      FS_FLOATS
#define SC_WARP     768
#define CS_OFF      (SC_OFF + WARPS*SC_WARP)
#define CS_WARP     576
#define GB_OFF      (CS_OFF + WARPS*CS_WARP)
#define GB_WARP     592               // Wp: 2 samples x 32 rows x 9 words = 576 used
#define WV_OFF      (GB_OFF + WARPS*GB_WARP)
#define SMEM_FLOATS (WV_OFF + WARPS*384)
#define SMEM_BYTES  (SMEM_FLOATS*4)   // 109056 B -> 2 CTAs/SM

__device__ __align__(16) unsigned g_Fh[HN*KN];        // [h][k] = half2(Bd, Bdd)
__device__ __align__(16) float4 g_PT4[(HN/2)*KN];
__device__ __align__(16) float2 g_Mp[KN*32];
__device__ __align__(16) float  g_CW[(NSAMP/2)*768];

// ---- helpers ----
__device__ __forceinline__ ull ffma2(ull a, ull b, ull c){
    ull d; asm("fma.rn.f32x2 %0,%1,%2,%3;" : "=l"(d) : "l"(a), "l"(b), "l"(c)); return d;
}
__device__ __forceinline__ void funpack(ull u, float& x, float& y){
    asm("mov.b64 {%0,%1},%2;" : "=f"(x), "=f"(y) : "l"(u));
}
__device__ __forceinline__ ull fdup(float x){
    ull r; asm("mov.b64 %0,{%1,%1};" : "=l"(r) : "f"(x)); return r;
}
__device__ __forceinline__ float rsqrt_fma(float x){
    float y = __uint_as_float(0x5f3759dfu - (__float_as_uint(x) >> 1));
    y = y * (1.5f - 0.5f*x*y*y);
    y = y * (1.5f - 0.5f*x*y*y);
    return y;
}
__device__ __forceinline__ unsigned f2hbits(float x){
    return (unsigned)__half_as_ushort(__float2half_rn(x));
}
__device__ __forceinline__ unsigned packg(float lo, float hi){
    float a = fminf(fmaxf(lo*GSCALE, -60000.f), 60000.f);
    float b = fminf(fmaxf(hi*GSCALE, -60000.f), 60000.f);
    return f2hbits(a) | (f2hbits(b) << 16);
}
__device__ __forceinline__ void cpasync16(unsigned smem_dst, const void* gsrc){
    asm volatile("cp.async.cg.shared.global [%0], [%1], 16;" :: "r"(smem_dst), "l"(gsrc));
}
#define CPASYNC_COMMIT() asm volatile("cp.async.commit_group;")
#define CPASYNC_WAIT0()  asm volatile("cp.async.wait_group 0;")

#define MMA16816(d, a0, a1, a2, a3, b0, b1) \
    asm volatile("mma.sync.aligned.m16n8k16.row.col.f32.f16.f16.f32 " \
        "{%0,%1,%2,%3}, {%4,%5,%6,%7}, {%8,%9}, {%0,%1,%2,%3};" \
        : "+f"(d[0]), "+f"(d[1]), "+f"(d[2]), "+f"(d[3]) \
        : "r"(a0), "r"(a1), "r"(a2), "r"(a3), "r"(b0), "r"(b1))

#define LDSM4(a0,a1,a2,a3,addr) \
    asm volatile("ldmatrix.sync.aligned.m8n8.x4.shared.b16 {%0,%1,%2,%3}, [%4];" \
        : "=r"(a0),"=r"(a1),"=r"(a2),"=r"(a3) : "r"(addr))

#define LDSM4T(a0,a1,a2,a3,addr) \
    asm volatile("ldmatrix.sync.aligned.m8n8.x4.trans.shared.b16 {%0,%1,%2,%3}, [%4];" \
        : "=r"(a0),"=r"(a1),"=r"(a2),"=r"(a3) : "r"(addr))

// K1: prep + gram (unchanged, proven)
__global__ void prep_kernel(const float* __restrict__ B,
                            const float* __restrict__ Bd,
                            const float* __restrict__ Bdd,
                            const float* __restrict__ Bddd,
                            const float* __restrict__ Bpinv,
                            const float* __restrict__ lambdas)
{
    int bid = blockIdx.x, t = threadIdx.x;
    if (bid < 128) {
        int idx = bid*256 + t;
        __half2 hv = __halves2half2(__float2half(Bd[idx]), __float2half(Bdd[idx]));
        g_Fh[idx] = *(unsigned*)&hv;
        if (idx < (HN/2)*KN) {
            int hp = idx >> 6, k = idx & 63;
            int h0 = 2*hp, h1 = 2*hp + 1;
            g_PT4[idx] = make_float4(Bpinv[k*HN + h0], B[h0*KN + k],
                                     Bpinv[k*HN + h1], B[h1*KN + k]);
        }
    } else {
        __shared__ float pab[4][KN], paj[4][KN], Mrow[KN];
        int kk = bid - 128;
        int k2 = t & 63, part = t >> 6;
        float ab0=0.f, ab1=0.f, ab2=0.f, ab3=0.f;
        float aj0=0.f, aj1=0.f, aj2=0.f, aj3=0.f;
        int h0 = part*128;
        #pragma unroll 4
        for (int h = h0; h < h0 + 128; h += 4) {
            ab0 += B[(h+0)*KN + kk]    * B[(h+0)*KN + k2];
            ab1 += B[(h+1)*KN + kk]    * B[(h+1)*KN + k2];
            ab2 += B[(h+2)*KN + kk]    * B[(h+2)*KN + k2];
            ab3 += B[(h+3)*KN + kk]    * B[(h+3)*KN + k2];
            aj0 += Bddd[(h+0)*KN + kk] * Bddd[(h+0)*KN + k2];
            aj1 += Bddd[(h+1)*KN + kk] * Bddd[(h+1)*KN + k2];
            aj2 += Bddd[(h+2)*KN + kk] * Bddd[(h+2)*KN + k2];
            aj3 += Bddd[(h+3)*KN + kk] * Bddd[(h+3)*KN + k2];
        }
        pab[part][k2] = (ab0+ab1) + (ab2+ab3);
        paj[part][k2] = (aj0+aj1) + (aj2+aj3);
        __syncthreads();
        if (t < KN) {
            float sab = pab[0][t]+pab[1][t]+pab[2][t]+pab[3][t];
            float saj = paj[0][t]+paj[1][t]+paj[2][t]+paj[3][t];
            Mrow[t] = 2.f * (lambdas[0]*sab + lambdas[2]*saj);
        }
        __syncthreads();
        if (t < 32) g_Mp[kk*32 + t] = make_float2(Mrow[t], Mrow[t+32]);
    }
}

// K2: init matvecs (unchanged, proven)
__global__ __launch_bounds__(256)
void init_kernel(const float* __restrict__ R_U,
                 const float* __restrict__ lambdas)
{
    const int w = threadIdx.x >> 5;
    const int l = threadIdx.x & 31;
    const int pair = blockIdx.x * WARPS + w;
    const int sA = pair*2, sB = sA + 1;
    const float l1 = lambdas[0];

    ull accw[2][2][3] = {{{0,0,0},{0,0,0}},{{0,0,0},{0,0,0}}};
    const float4* rpA = (const float4*)(R_U + (size_t)sA * (HN*3));
    const float4* rpB = (const float4*)(R_U + (size_t)sB * (HN*3));
    #pragma unroll 1
    for (int q = 0; q < HN/4; q++) {
        ulonglong2 u00 = *(const ulonglong2*)&g_PT4[(2*q  )*KN + l];
        ulonglong2 u01 = *(const ulonglong2*)&g_PT4[(2*q  )*KN + l + 32];
        ulonglong2 u10 = *(const ulonglong2*)&g_PT4[(2*q+1)*KN + l];
        ulonglong2 u11 = *(const ulonglong2*)&g_PT4[(2*q+1)*KN + l + 32];
        #pragma unroll
        for (int s = 0; s < 2; s++) {
            const float4* rp = s ? rpB : rpA;
            float4 r0 = rp[3*q], r1 = rp[3*q+1], r2 = rp[3*q+2];
            float rr[12] = {r0.x,r0.y,r0.z,r0.w, r1.x,r1.y,r1.z,r1.w, r2.x,r2.y,r2.z,r2.w};
            #pragma unroll
            for (int j = 0; j < 3; j++) {
                ull d0 = fdup(rr[j]);
                ull d1 = fdup(rr[3+j]);
                ull d2 = fdup(rr[6+j]);
                ull d3 = fdup(rr[9+j]);
                accw[s][0][j] = ffma2(u00.x, d0, accw[s][0][j]);
                accw[s][0][j] = ffma2(u00.y, d1, accw[s][0][j]);
                accw[s][0][j] = ffma2(u10.x, d2, accw[s][0][j]);
                accw[s][0][j] = ffma2(u10.y, d3, accw[s][0][j]);
                accw[s][1][j] = ffma2(u01.x, d0, accw[s][1][j]);
                accw[s][1][j] = ffma2(u01.y, d1, accw[s][1][j]);
                accw[s][1][j] = ffma2(u11.x, d2, accw[s][1][j]);
                accw[s][1][j] = ffma2(u11.y, d3, accw[s][1][j]);
            }
        }
    }
    float val[24];
    #pragma unroll
    for (int s = 0; s < 2; s++)
        #pragma unroll
        for (int k = 0; k < 2; k++)
            #pragma unroll
            for (int j = 0; j < 3; j++) {
                float cv, wvr;
                funpack(accw[s][k][j], cv, wvr);
                val[s*6 + k*3 + j]      = cv;
                val[12 + s*6 + k*3 + j] = -2.f*l1*wvr;
            }
    float4* cw = (float4*)(g_CW + (size_t)pair*768);
    #pragma unroll
    for (int q = 0; q < 6; q++)
        cw[q*32 + l] = make_float4(val[4*q], val[4*q+1], val[4*q+2], val[4*q+3]);
}

// Elementwise gradient (unchanged)
__device__ __forceinline__ void elemgrad(
    float v0, float v1, float v2,
    float a0, float a1, float a2,
    float aa, float bb, float l2, float* g)
{
    float vsq = v0*v0 + v1*v1 + v2*v2;
    float inv_vn = vsq > 0.f ? rsqrt_fma(vsq) : 0.f;
    float vn  = vsq * inv_vn;
    float vne = vn + EPSF;

    float cx = v1*a2 - v2*a1;
    float cy = v2*a0 - v0*a2;
    float cz = v0*a1 - v1*a0;
    float csq = cx*cx + cy*cy + cz*cz;
    float inv_cn = csq > 0.f ? rsqrtf(csq) : 0.f;
    float cn = csq * inv_cn;

    float inv_den = inv_vn * inv_vn * inv_vn;
    float kappa = cn * inv_den;

    float ks  = fminf(fmaxf(kappa, 1e-4f), 1e4f);
    float lpr = bb * __logf(ks);
    float lp  = fminf(fmaxf(lpr, -10.f), 10.f);
    float traw   = aa * __expf(lp);
    float target = fminf(fmaxf(traw, 1e-6f), 1e6f);

    float u   = vn - target;
    float gvn = 2.f * l2 * u;
    float gt  = (traw > 1e-6f && traw < 1e6f) ? (-2.f * l2 * u) : 0.f;
    float glk = ((lpr > -10.f && lpr < 10.f) ? gt * traw : 0.f) * bb;
    float gk  = (kappa > 1e-4f && kappa < 1e4f) ? glk : 0.f;
    float gcn  = gk * inv_cn;
    float gden = -gk * inv_den;
    gvn += gden * 3.f * vne * vne;

    float scr = gcn * inv_cn;
    float gc0 = scr * cx, gc1 = scr * cy, gc2 = scr * cz;
    float sV = gvn * inv_vn;
    g[0] = sV*v0 + a1*gc2 - a2*gc1;
    g[1] = sV*v1 + a2*gc0 - a0*gc2;
    g[2] = sV*v2 + a0*gc1 - a1*gc0;
    g[3] = gc1*v2 - gc2*v1;
    g[4] = gc2*v0 - gc0*v2;
    g[5] = gc0*v1 - gc1*v0;
}

// K3: main. Tensor fwd + bwd (R14-proven); cp.async double-buffered staging.
__global__ __launch_bounds__(256, 2)
void inner_opt_kernel(const float* __restrict__ alpha,
                      const float* __restrict__ beta,
                      const float* __restrict__ lambdas,
                      float* __restrict__ out)
{
    extern __shared__ __align__(16) float smem[];
    char* FhBase = (char*)smem;                             // 2 x [CHK][272 B]
    const int w = threadIdx.x >> 5;
    const int l = threadIdx.x & 31;
    float* ScW = smem + SC_OFF + w*SC_WARP;
    float* Cq  = smem + CS_OFF + w*CS_WARP;
    unsigned* Wp = (unsigned*)(smem + GB_OFF + w*GB_WARP);  // [2][32][9] fp16x2 words
    float*  Ws  = smem + WV_OFF + w*384;

    const int pair = blockIdx.x * WARPS + w;
    const int sA = pair*2;
    const int sB = sA + 1;
    const int k0 = l, k1 = l + 32;
    const int qa = l >> 2, la3 = (l & 3) * 3;

    const float l2 = lambdas[1];
    const float aaA = alpha[sA], bbA = beta[sA];
    const float aaB = alpha[sB], bbB = beta[sB];

    const unsigned fsh0 = (unsigned)__cvta_generic_to_shared(FhBase);
    const unsigned fsh1 = fsh0 + FBUF_B;

    // staging lane constants
    const int st_t = threadIdx.x;
    const unsigned st_dst = (unsigned)((st_t >> 4)*272 + (st_t & 15)*16);

    // ---- prologue: async-stage chunk 0 into buffer 0 ----
    {
        const char* src = (const char*)g_Fh;
        #pragma unroll
        for (int i = 0; i < 4; i++) {
            int idx = st_t + 256*i;
            unsigned d = fsh0 + (unsigned)((idx >> 4)*272 + (idx & 15)*16);
            cpasync16(d, src + idx*16);
        }
        CPASYNC_COMMIT();
    }

    // ---- load precomputed (c, -wv) (overlaps the async stage) ----
    {
        const float4* cw = (const float4*)(g_CW + (size_t)pair*768);
        float val[24];
        #pragma unroll
        for (int q = 0; q < 6; q++) {
            float4 v = cw[q*32 + l];
            val[4*q+0] = v.x; val[4*q+1] = v.y; val[4*q+2] = v.z; val[4*q+3] = v.w;
        }
        #pragma unroll
        for (int s = 0; s < 2; s++)
            #pragma unroll
            for (int k = 0; k < 2; k++) {
                int slot = (qa + (k ? 8 : 0))*36 + s*16 + la3;
                #pragma unroll
                for (int j = 0; j < 3; j++) {
                    Cq[slot + j] = val[s*6 + k*3 + j];
                    Ws[l*12 + s*6 + k*3 + j] = val[12 + s*6 + k*3 + j];
                }
            }
    }
    CPASYNC_WAIT0();
    __syncthreads();

    // lane constants: fwd B-frag build
    const int nfb = l >> 2;
    const bool fb_lo = (nfb < 3);
    const bool fb_hi = (nfb >= 3 && nfb < 6);
    const int fb_j  = fb_lo ? nfb : (fb_hi ? nfb - 3 : 0);
    const int fb_off = (l & 3)*3 + fb_j;
    // lane constants: bwd ldmatrix.trans base offset
    const unsigned bwd_off = (unsigned)(((l & 7) + ((l & 16) ? 8 : 0))*272
                                        + ((l & 8) ? 8 : 0)*2);
    // lane constants: bwd B-frag word indices
    const int wb0 = (l & 3)*9 + (l >> 2);
    const int wb1 = ((l & 3) + 4)*9 + (l >> 2);

    int gi = 0;   // global chunk counter 0..23
    for (int step = 0; step < 3; step++) {
        float accD[2][8][4];
        #pragma unroll
        for (int s = 0; s < 2; s++)
            #pragma unroll
            for (int mt = 0; mt < 8; mt++)
                #pragma unroll
                for (int e = 0; e < 4; e++)
                    accD[s][mt][e] = 0.f;

        for (int ch = 0; ch < NCHUNK; ch++) {
            const unsigned fsh = (gi & 1) ? fsh1 : fsh0;

            // ---- prefetch next chunk into the other buffer (async) ----
            if (gi < 3*NCHUNK - 1) {
                const char* src = (const char*)(g_Fh + (((gi + 1) & (NCHUNK-1)) * CHK)*KN);
                unsigned dbase = ((gi + 1) & 1) ? fsh1 : fsh0;
                #pragma unroll
                for (int i = 0; i < 4; i++) {
                    cpasync16(dbase + st_dst + (unsigned)(i*4352),
                              src + st_t*16 + i*4096);
                }
                CPASYNC_COMMIT();
            }

            // ---- Phase A (tensor fwd): D[64x8] = Ftile @ Bmat(C) ----
            {
                unsigned bf[2][8][2];
                #pragma unroll
                for (int kt = 0; kt < 8; kt++)
                    #pragma unroll
                    for (int s = 0; s < 2; s++) {
                        unsigned h0 = f2hbits(Cq[(2*kt  )*36 + s*16 + fb_off]);
                        unsigned h1 = f2hbits(Cq[(2*kt+1)*36 + s*16 + fb_off]);
                        bf[s][kt][0] = fb_lo ? h0 : (fb_hi ? (h0 << 16) : 0u);
                        bf[s][kt][1] = fb_lo ? h1 : (fb_hi ? (h1 << 16) : 0u);
                    }
                #pragma unroll
                for (int mt = 0; mt < 4; mt++) {
                    float dA[4] = {0.f,0.f,0.f,0.f};
                    float dB[4] = {0.f,0.f,0.f,0.f};
                    unsigned arow = fsh + (unsigned)((16*mt + (l & 15))*272 + (l >> 4)*16);
                    #pragma unroll
                    for (int kt = 0; kt < 8; kt++) {
                        unsigned a0, a1, a2, a3;
                        LDSM4(a0, a1, a2, a3, arow + (unsigned)(kt*32));
                        MMA16816(dA, a0, a1, a2, a3, bf[0][kt][0], bf[0][kt][1]);
                        MMA16816(dB, a0, a1, a2, a3, bf[1][kt][0], bf[1][kt][1]);
                    }
                    if ((l & 3) < 3) {
                        int r0 = 16*mt + (l >> 2);
                        int cc = 2*(l & 3);
                        *(float2*)(ScW + r0*6 + cc)           = make_float2(dA[0], dA[1]);
                        *(float2*)(ScW + (r0+8)*6 + cc)       = make_float2(dA[2], dA[3]);
                        *(float2*)(ScW + 384 + r0*6 + cc)     = make_float2(dB[0], dB[1]);
                        *(float2*)(ScW + 384 + (r0+8)*6 + cc) = make_float2(dB[2], dB[3]);
                    }
                }
                __syncwarp();

                float g0[6], g1[6];
                #pragma unroll
                for (int s = 0; s < 2; s++) {
                    const float* sc = ScW + s*384;
                    unsigned* wp = Wp + s*288;
                    float aa = s ? aaB : aaA;
                    float bb = s ? bbB : bbA;
                    float4 qaV = *(const float4*)(sc + 12*l);
                    float2 qbV = *(const float2*)(sc + 12*l + 4);
                    elemgrad(qaV.x, qaV.y, qaV.z, qaV.w, qbV.x, qbV.y, aa, bb, l2, g0);
                    float2 qcV = *(const float2*)(sc + 12*l + 6);
                    float4 qdV = *(const float4*)(sc + 12*l + 8);
                    elemgrad(qcV.x, qcV.y, qdV.x, qdV.y, qdV.z, qdV.w, aa, bb, l2, g1);
                    #pragma unroll
                    for (int n = 0; n < 6; n++)
                        wp[l*9 + n] = packg(g0[n], g1[n]);
                    wp[l*9 + 6] = 0u;
                    wp[l*9 + 7] = 0u;
                }
            }
            __syncwarp();

            // ---- Phase B (tensor bwd): accD += Ftile^T @ G' ----
            {
                #pragma unroll
                for (int kt = 0; kt < 4; kt++) {
                    unsigned bA0 = Wp[8*kt*9 + wb0];
                    unsigned bA1 = Wp[8*kt*9 + wb1];
                    unsigned bB0 = Wp[288 + 8*kt*9 + wb0];
                    unsigned bB1 = Wp[288 + 8*kt*9 + wb1];
                    unsigned abase = fsh + bwd_off + (unsigned)(16*kt*272);
                    #pragma unroll
                    for (int mt = 0; mt < 8; mt++) {
                        unsigned a0, a1, a2, a3;
                        LDSM4T(a0, a1, a2, a3, abase + (unsigned)(mt*32));
                        MMA16816(accD[0][mt], a0, a1, a2, a3, bA0, bA1);
                        MMA16816(accD[1][mt], a0, a1, a2, a3, bB0, bB1);
                    }
                }
            }

            CPASYNC_WAIT0();
            __syncthreads();   // next chunk staged; current buffer free next iter
            gi++;
        }

        // ---- Phase C: mc = M @ C ----
        ull mca[2][3] = {{0,0,0},{0,0,0}};
        {
            #pragma unroll 2
            for (int q = 0; q < 16; q++) {
                const float* cqp = Cq + q*36;
                float4 a0 = *(const float4*)(cqp);
                float4 a1 = *(const float4*)(cqp + 4);
                float4 a2 = *(const float4*)(cqp + 8);
                float4 b0 = *(const float4*)(cqp + 16);
                float4 b1 = *(const float4*)(cqp + 20);
                float4 b2 = *(const float4*)(cqp + 24);
                float cA[12] = {a0.x,a0.y,a0.z,a0.w, a1.x,a1.y,a1.z,a1.w, a2.x,a2.y,a2.z,a2.w};
                float cB[12] = {b0.x,b0.y,b0.z,b0.w, b1.x,b1.y,b1.z,b1.w, b2.x,b2.y,b2.z,b2.w};
                #pragma unroll
                for (int i = 0; i < 4; i++) {
                    int kk = 4*q + i;
                    ull pm = *(const ull*)&g_Mp[kk*32 + l];
                    mca[0][0] = ffma2(pm, fdup(cA[i*3+0]), mca[0][0]);
                    mca[0][1] = ffma2(pm, fdup(cA[i*3+1]), mca[0][1]);
                    mca[0][2] = ffma2(pm, fdup(cA[i*3+2]), mca[0][2]);
                    mca[1][0] = ffma2(pm, fdup(cB[i*3+0]), mca[1][0]);
                    mca[1][1] = ffma2(pm, fdup(cB[i*3+1]), mca[1][1]);
                    mca[1][2] = ffma2(pm, fdup(cB[i*3+2]), mca[1][2]);
                }
            }
        }
        __syncwarp();

        // ---- per sample: extract D, combine, SGD update ----
        #pragma unroll
        for (int s = 0; s < 2; s++) {
            #pragma unroll
            for (int mt = 0; mt < 8; mt++) {
                if ((l & 3) < 3) {
                    int r0 = 16*mt + (l >> 2);
                    int n2 = 2*(l & 3);
                    *(float2*)(ScW + r0*6 + n2) =
                        make_float2(accD[s][mt][0]*GBACK, accD[s][mt][1]*GBACK);
                    *(float2*)(ScW + (r0+8)*6 + n2) =
                        make_float2(accD[s][mt][2]*GBACK, accD[s][mt][3]*GBACK);
                }
            }
            __syncwarp();
            float m0f, m1f;
            #pragma unroll
            for (int k = 0; k < 2; k++) {
                int kk = k ? k1 : k0;
                int slot = (qa + (k ? 8 : 0))*36 + s*16 + la3;
                #pragma unroll
                for (int j = 0; j < 3; j++) {
                    float dval = ScW[(2*kk)*6 + j] + ScW[(2*kk+1)*6 + 3 + j];
                    funpack(mca[s][j], m0f, m1f);
                    float m = k ? m1f : m0f;
                    float negwv = Ws[l*12 + s*6 + k*3 + j];
                    Cq[slot + j] = Cq[slot + j] - LRATE * (dval + m + negwv);
                }
            }
            __syncwarp();
        }
    }

    // ---- output (from Cq) ----
    #pragma unroll
    for (int s = 0; s < 2; s++) {
        float* op = out + (size_t)(sA + s) * (KN*3);
        #pragma unroll
        for (int k = 0; k < 2; k++) {
            int kk = k ? k1 : k0;
            int slot = (qa + (k ? 8 : 0))*36 + s*16 + la3;
            #pragma unroll
            for (int j = 0; j < 3; j++)
                op[kk*3 + j] = Cq[slot + j];
        }
    }
}

extern "C" void kernel_launch(void* const* d_in, const int* in_sizes, int n_in,
                              void* d_out, int out_size)
{
    const float* R_U     = (const float*)d_in[0];
    const float* alpha   = (const float*)d_in[1];
    const float* beta    = (const float*)d_in[2];
    const float* lambdas = (const float*)d_in[3];
    const float* B       = (const float*)d_in[4];
    const float* Bd      = (const float*)d_in[5];
    const float* Bdd     = (const float*)d_in[6];
    const float* Bddd    = (const float*)d_in[7];
    const float* Bpinv   = (const float*)d_in[8];

    cudaFuncSetAttribute(inner_opt_kernel,
                         cudaFuncAttributeMaxDynamicSharedMemorySize, SMEM_BYTES);

    prep_kernel<<<192, 256>>>(B, Bd, Bdd, Bddd, Bpinv, lambdas);
    init_kernel<<<NSAMP/(WARPS*2), 256>>>(R_U, lambdas);
    inner_opt_kernel<<<NSAMP/(WARPS*2), 256, SMEM_BYTES>>>(
        alpha, beta, lambdas, (float*)d_out);
}

// round 16
// speedup vs baseline: 1.9470x; 1.0491x over previous
#include <cuda_runtime.h>
#include <cuda_fp16.h>

typedef unsigned long long ull;

#define HN 512
#define KN 64
#define NSAMP 16384
#define LRATE 0.001f
#define EPSF 1e-8f
#define WARPS 8
#define CHK 64
#define NCHUNK (HN/CHK)
#define FH_H2 68                      // half2 per staged row (272 B)
#define FBUF_B (CHK*272)              // 17408 B per F buffer
#define GSCALE 0.00390625f            // 2^-8 G scaling for fp16 range
#define GBACK  256.0f

// smem layout (float units)
#define FS_FLOATS   (2*CHK*FH_H2)     // 8704 (double-buffered fp16 F)
#define SC_OFF      FS_FLOATS
#define SC_WARP     768
#define CS_OFF      (SC_OFF + WARPS*SC_WARP)
#define CS_WARP     576
#define GB_OFF      (CS_OFF + WARPS*CS_WARP)
#define GB_WARP     592               // Wp: 2 samples x 32 rows x 9 words = 576 used
#define WV_OFF      (GB_OFF + WARPS*GB_WARP)
#define SMEM_FLOATS (WV_OFF + WARPS*384)
#define SMEM_BYTES  (SMEM_FLOATS*4)   // 109056 B -> 2 CTAs/SM

__device__ __align__(16) unsigned g_Fh[HN*KN];        // [h][k] = half2(Bd, Bdd)
__device__ __align__(16) float4 g_PT4[(HN/2)*KN];
__device__ __align__(16) float2 g_Mp[KN*32];
__device__ __align__(16) float  g_CW[(NSAMP/2)*768];

// ---- helpers ----
__device__ __forceinline__ ull ffma2(ull a, ull b, ull c){
    ull d; asm("fma.rn.f32x2 %0,%1,%2,%3;" : "=l"(d) : "l"(a), "l"(b), "l"(c)); return d;
}
__device__ __forceinline__ void funpack(ull u, float& x, float& y){
    asm("mov.b64 {%0,%1},%2;" : "=f"(x), "=f"(y) : "l"(u));
}
__device__ __forceinline__ ull fdup(float x){
    ull r; asm("mov.b64 %0,{%1,%1};" : "=l"(r) : "f"(x)); return r;
}
__device__ __forceinline__ float rsqrt_fma(float x){
    float y = __uint_as_float(0x5f3759dfu - (__float_as_uint(x) >> 1));
    y = y * (1.5f - 0.5f*x*y*y);
    y = y * (1.5f - 0.5f*x*y*y);
    return y;
}
// packed fp16x2 convert: lo16 = h(lo), hi16 = h(hi), round-to-nearest
__device__ __forceinline__ unsigned cvt2h(float lo, float hi){
    unsigned r; asm("cvt.rn.f16x2.f32 %0, %1, %2;" : "=r"(r) : "f"(hi), "f"(lo));
    return r;
}
__device__ __forceinline__ unsigned packg(float lo, float hi){
    float a = fminf(fmaxf(lo*GSCALE, -60000.f), 60000.f);
    float b = fminf(fmaxf(hi*GSCALE, -60000.f), 60000.f);
    return cvt2h(a, b);
}
__device__ __forceinline__ unsigned prmt0(unsigned a, unsigned sel){
    unsigned d; asm("prmt.b32 %0, %1, 0, %2;" : "=r"(d) : "r"(a), "r"(sel));
    return d;
}
__device__ __forceinline__ void cpasync16(unsigned smem_dst, const void* gsrc){
    asm volatile("cp.async.cg.shared.global [%0], [%1], 16;" :: "r"(smem_dst), "l"(gsrc));
}
#define CPASYNC_COMMIT() asm volatile("cp.async.commit_group;")
#define CPASYNC_WAIT0()  asm volatile("cp.async.wait_group 0;")

#define MMA16816(d, a0, a1, a2, a3, b0, b1) \
    asm volatile("mma.sync.aligned.m16n8k16.row.col.f32.f16.f16.f32 " \
        "{%0,%1,%2,%3}, {%4,%5,%6,%7}, {%8,%9}, {%0,%1,%2,%3};" \
        : "+f"(d[0]), "+f"(d[1]), "+f"(d[2]), "+f"(d[3]) \
        : "r"(a0), "r"(a1), "r"(a2), "r"(a3), "r"(b0), "r"(b1))

#define LDSM4(a0,a1,a2,a3,addr) \
    asm volatile("ldmatrix.sync.aligned.m8n8.x4.shared.b16 {%0,%1,%2,%3}, [%4];" \
        : "=r"(a0),"=r"(a1),"=r"(a2),"=r"(a3) : "r"(addr))

#define LDSM4T(a0,a1,a2,a3,addr) \
    asm volatile("ldmatrix.sync.aligned.m8n8.x4.trans.shared.b16 {%0,%1,%2,%3}, [%4];" \
        : "=r"(a0),"=r"(a1),"=r"(a2),"=r"(a3) : "r"(addr))

// K1: prep + gram (unchanged, proven)
__global__ void prep_kernel(const float* __restrict__ B,
                            const float* __restrict__ Bd,
                            const float* __restrict__ Bdd,
                            const float* __restrict__ Bddd,
                            const float* __restrict__ Bpinv,
                            const float* __restrict__ lambdas)
{
    int bid = blockIdx.x, t = threadIdx.x;
    if (bid < 128) {
        int idx = bid*256 + t;
        __half2 hv = __halves2half2(__float2half(Bd[idx]), __float2half(Bdd[idx]));
        g_Fh[idx] = *(unsigned*)&hv;
        if (idx < (HN/2)*KN) {
            int hp = idx >> 6, k = idx & 63;
            int h0 = 2*hp, h1 = 2*hp + 1;
            g_PT4[idx] = make_float4(Bpinv[k*HN + h0], B[h0*KN + k],
                                     Bpinv[k*HN + h1], B[h1*KN + k]);
        }
    } else {
        __shared__ float pab[4][KN], paj[4][KN], Mrow[KN];
        int kk = bid - 128;
        int k2 = t & 63, part = t >> 6;
        float ab0=0.f, ab1=0.f, ab2=0.f, ab3=0.f;
        float aj0=0.f, aj1=0.f, aj2=0.f, aj3=0.f;
        int h0 = part*128;
        #pragma unroll 4
        for (int h = h0; h < h0 + 128; h += 4) {
            ab0 += B[(h+0)*KN + kk]    * B[(h+0)*KN + k2];
            ab1 += B[(h+1)*KN + kk]    * B[(h+1)*KN + k2];
            ab2 += B[(h+2)*KN + kk]    * B[(h+2)*KN + k2];
            ab3 += B[(h+3)*KN + kk]    * B[(h+3)*KN + k2];
            aj0 += Bddd[(h+0)*KN + kk] * Bddd[(h+0)*KN + k2];
            aj1 += Bddd[(h+1)*KN + kk] * Bddd[(h+1)*KN + k2];
            aj2 += Bddd[(h+2)*KN + kk] * Bddd[(h+2)*KN + k2];
            aj3 += Bddd[(h+3)*KN + kk] * Bddd[(h+3)*KN + k2];
        }
        pab[part][k2] = (ab0+ab1) + (ab2+ab3);
        paj[part][k2] = (aj0+aj1) + (aj2+aj3);
        __syncthreads();
        if (t < KN) {
            float sab = pab[0][t]+pab[1][t]+pab[2][t]+pab[3][t];
            float saj = paj[0][t]+paj[1][t]+paj[2][t]+paj[3][t];
            Mrow[t] = 2.f * (lambdas[0]*sab + lambdas[2]*saj);
        }
        __syncthreads();
        if (t < 32) g_Mp[kk*32 + t] = make_float2(Mrow[t], Mrow[t+32]);
    }
}

// K2: init matvecs (unchanged, proven)
__global__ __launch_bounds__(256)
void init_kernel(const float* __restrict__ R_U,
                 const float* __restrict__ lambdas)
{
    const int w = threadIdx.x >> 5;
    const int l = threadIdx.x & 31;
    const int pair = blockIdx.x * WARPS + w;
    const int sA = pair*2, sB = sA + 1;
    const float l1 = lambdas[0];

    ull accw[2][2][3] = {{{0,0,0},{0,0,0}},{{0,0,0},{0,0,0}}};
    const float4* rpA = (const float4*)(R_U + (size_t)sA * (HN*3));
    const float4* rpB = (const float4*)(R_U + (size_t)sB * (HN*3));
    #pragma unroll 1
    for (int q = 0; q < HN/4; q++) {
        ulonglong2 u00 = *(const ulonglong2*)&g_PT4[(2*q  )*KN + l];
        ulonglong2 u01 = *(const ulonglong2*)&g_PT4[(2*q  )*KN + l + 32];
        ulonglong2 u10 = *(const ulonglong2*)&g_PT4[(2*q+1)*KN + l];
        ulonglong2 u11 = *(const ulonglong2*)&g_PT4[(2*q+1)*KN + l + 32];
        #pragma unroll
        for (int s = 0; s < 2; s++) {
            const float4* rp = s ? rpB : rpA;
            float4 r0 = rp[3*q], r1 = rp[3*q+1], r2 = rp[3*q+2];
            float rr[12] = {r0.x,r0.y,r0.z,r0.w, r1.x,r1.y,r1.z,r1.w, r2.x,r2.y,r2.z,r2.w};
            #pragma unroll
            for (int j = 0; j < 3; j++) {
                ull d0 = fdup(rr[j]);
                ull d1 = fdup(rr[3+j]);
                ull d2 = fdup(rr[6+j]);
                ull d3 = fdup(rr[9+j]);
                accw[s][0][j] = ffma2(u00.x, d0, accw[s][0][j]);
                accw[s][0][j] = ffma2(u00.y, d1, accw[s][0][j]);
                accw[s][0][j] = ffma2(u10.x, d2, accw[s][0][j]);
                accw[s][0][j] = ffma2(u10.y, d3, accw[s][0][j]);
                accw[s][1][j] = ffma2(u01.x, d0, accw[s][1][j]);
                accw[s][1][j] = ffma2(u01.y, d1, accw[s][1][j]);
                accw[s][1][j] = ffma2(u11.x, d2, accw[s][1][j]);
                accw[s][1][j] = ffma2(u11.y, d3, accw[s][1][j]);
            }
        }
    }
    float val[24];
    #pragma unroll
    for (int s = 0; s < 2; s++)
        #pragma unroll
        for (int k = 0; k < 2; k++)
            #pragma unroll
            for (int j = 0; j < 3; j++) {
                float cv, wvr;
                funpack(accw[s][k][j], cv, wvr);
                val[s*6 + k*3 + j]      = cv;
                val[12 + s*6 + k*3 + j] = -2.f*l1*wvr;
            }
    float4* cw = (float4*)(g_CW + (size_t)pair*768);
    #pragma unroll
    for (int q = 0; q < 6; q++)
        cw[q*32 + l] = make_float4(val[4*q], val[4*q+1], val[4*q+2], val[4*q+3]);
}

// Elementwise gradient (unchanged)
__device__ __forceinline__ void elemgrad(
    float v0, float v1, float v2,
    float a0, float a1, float a2,
    float aa, float bb, float l2, float* g)
{
    float vsq = v0*v0 + v1*v1 + v2*v2;
    float inv_vn = vsq > 0.f ? rsqrt_fma(vsq) : 0.f;
    float vn  = vsq * inv_vn;
    float vne = vn + EPSF;

    float cx = v1*a2 - v2*a1;
    float cy = v2*a0 - v0*a2;
    float cz = v0*a1 - v1*a0;
    float csq = cx*cx + cy*cy + cz*cz;
    float inv_cn = csq > 0.f ? rsqrtf(csq) : 0.f;
    float cn = csq * inv_cn;

    float inv_den = inv_vn * inv_vn * inv_vn;
    float kappa = cn * inv_den;

    float ks  = fminf(fmaxf(kappa, 1e-4f), 1e4f);
    float lpr = bb * __logf(ks);
    float lp  = fminf(fmaxf(lpr, -10.f), 10.f);
    float traw   = aa * __expf(lp);
    float target = fminf(fmaxf(traw, 1e-6f), 1e6f);

    float u   = vn - target;
    float gvn = 2.f * l2 * u;
    float gt  = (traw > 1e-6f && traw < 1e6f) ? (-2.f * l2 * u) : 0.f;
    float glk = ((lpr > -10.f && lpr < 10.f) ? gt * traw : 0.f) * bb;
    float gk  = (kappa > 1e-4f && kappa < 1e4f) ? glk : 0.f;
    float gcn  = gk * inv_cn;
    float gden = -gk * inv_den;
    gvn += gden * 3.f * vne * vne;

    float scr = gcn * inv_cn;
    float gc0 = scr * cx, gc1 = scr * cy, gc2 = scr * cz;
    float sV = gvn * inv_vn;
    g[0] = sV*v0 + a1*gc2 - a2*gc1;
    g[1] = sV*v1 + a2*gc0 - a0*gc2;
    g[2] = sV*v2 + a0*gc1 - a1*gc0;
    g[3] = gc1*v2 - gc2*v1;
    g[4] = gc2*v0 - gc0*v2;
    g[5] = gc0*v1 - gc1*v0;
}

// K3: main. Tensor fwd + bwd, cp.async double-buffered; B-frag conversions
// hoisted per step (pkc regs), per-chunk build reduced to PRMT only.
__global__ __launch_bounds__(256, 2)
void inner_opt_kernel(const float* __restrict__ alpha,
                      const float* __restrict__ beta,
                      const float* __restrict__ lambdas,
                      float* __restrict__ out)
{
    extern __shared__ __align__(16) float smem[];
    char* FhBase = (char*)smem;                             // 2 x [CHK][272 B]
    const int w = threadIdx.x >> 5;
    const int l = threadIdx.x & 31;
    float* ScW = smem + SC_OFF + w*SC_WARP;
    float* Cq  = smem + CS_OFF + w*CS_WARP;
    unsigned* Wp = (unsigned*)(smem + GB_OFF + w*GB_WARP);  // [2][32][9] fp16x2 words
    float*  Ws  = smem + WV_OFF + w*384;

    const int pair = blockIdx.x * WARPS + w;
    const int sA = pair*2;
    const int sB = sA + 1;
    const int k0 = l, k1 = l + 32;
    const int qa = l >> 2, la3 = (l & 3) * 3;

    const float l2 = lambdas[1];
    const float aaA = alpha[sA], bbA = beta[sA];
    const float aaB = alpha[sB], bbB = beta[sB];

    const unsigned fsh0 = (unsigned)__cvta_generic_to_shared(FhBase);
    const unsigned fsh1 = fsh0 + FBUF_B;

    const int st_t = threadIdx.x;
    const unsigned st_dst = (unsigned)((st_t >> 4)*272 + (st_t & 15)*16);

    // ---- prologue: async-stage chunk 0 into buffer 0 ----
    {
        const char* src = (const char*)g_Fh;
        #pragma unroll
        for (int i = 0; i < 4; i++) {
            int idx = st_t + 256*i;
            unsigned d = fsh0 + (unsigned)((idx >> 4)*272 + (idx & 15)*16);
            cpasync16(d, src + idx*16);
        }
        CPASYNC_COMMIT();
    }

    // ---- load precomputed (c, -wv); zero G' pad columns once ----
    {
        const float4* cw = (const float4*)(g_CW + (size_t)pair*768);
        float val[24];
        #pragma unroll
        for (int q = 0; q < 6; q++) {
            float4 v = cw[q*32 + l];
            val[4*q+0] = v.x; val[4*q+1] = v.y; val[4*q+2] = v.z; val[4*q+3] = v.w;
        }
        #pragma unroll
        for (int s = 0; s < 2; s++)
            #pragma unroll
            for (int k = 0; k < 2; k++) {
                int slot = (qa + (k ? 8 : 0))*36 + s*16 + la3;
                #pragma unroll
                for (int j = 0; j < 3; j++) {
                    Cq[slot + j] = val[s*6 + k*3 + j];
                    Ws[l*12 + s*6 + k*3 + j] = val[12 + s*6 + k*3 + j];
                }
            }
        Wp[l*9 + 6] = 0u; Wp[l*9 + 7] = 0u;
        Wp[288 + l*9 + 6] = 0u; Wp[288 + l*9 + 7] = 0u;
    }
    CPASYNC_WAIT0();
    __syncthreads();

    // lane constants: fwd B-frag build
    const int nfb = l >> 2;
    const bool fb_lo = (nfb < 3);
    const bool fb_hi = (nfb >= 3 && nfb < 6);
    const int fb_j  = fb_lo ? nfb : (fb_hi ? nfb - 3 : 0);
    const int fb_off = (l & 3)*3 + fb_j;
    const unsigned sel0 = fb_lo ? 0x4410u : (fb_hi ? 0x1044u : 0x4444u);
    const unsigned sel1 = fb_lo ? 0x4432u : (fb_hi ? 0x3244u : 0x4444u);
    // lane constants: bwd
    const unsigned bwd_off = (unsigned)(((l & 7) + ((l & 16) ? 8 : 0))*272
                                        + ((l & 8) ? 8 : 0)*2);
    const int wb0 = (l & 3)*9 + (l >> 2);
    const int wb1 = ((l & 3) + 4)*9 + (l >> 2);

    int gi = 0;
    for (int step = 0; step < 3; step++) {
        // ---- hoisted per-step: packed fp16 C pairs for fwd B-frags ----
        unsigned pkc[2][8];
        #pragma unroll
        for (int kt = 0; kt < 8; kt++)
            #pragma unroll
            for (int s = 0; s < 2; s++)
                pkc[s][kt] = cvt2h(Cq[(2*kt)*36 + s*16 + fb_off],
                                   Cq[(2*kt+1)*36 + s*16 + fb_off]);

        float accD[2][8][4];
        #pragma unroll
        for (int s = 0; s < 2; s++)
            #pragma unroll
            for (int mt = 0; mt < 8; mt++)
                #pragma unroll
                for (int e = 0; e < 4; e++)
                    accD[s][mt][e] = 0.f;

        for (int ch = 0; ch < NCHUNK; ch++) {
            const unsigned fsh = (gi & 1) ? fsh1 : fsh0;

            // ---- prefetch next chunk (async) ----
            if (gi < 3*NCHUNK - 1) {
                const char* src = (const char*)(g_Fh + (((gi + 1) & (NCHUNK-1)) * CHK)*KN);
                unsigned dbase = ((gi + 1) & 1) ? fsh1 : fsh0;
                #pragma unroll
                for (int i = 0; i < 4; i++) {
                    cpasync16(dbase + st_dst + (unsigned)(i*4352),
                              src + st_t*16 + i*4096);
                }
                CPASYNC_COMMIT();
            }

            // ---- Phase A (tensor fwd) ----
            {
                unsigned bf[2][8][2];
                #pragma unroll
                for (int kt = 0; kt < 8; kt++)
                    #pragma unroll
                    for (int s = 0; s < 2; s++) {
                        bf[s][kt][0] = prmt0(pkc[s][kt], sel0);
                        bf[s][kt][1] = prmt0(pkc[s][kt], sel1);
                    }
                #pragma unroll
                for (int mt = 0; mt < 4; mt++) {
                    float dA[4] = {0.f,0.f,0.f,0.f};
                    float dB[4] = {0.f,0.f,0.f,0.f};
                    unsigned arow = fsh + (unsigned)((16*mt + (l & 15))*272 + (l >> 4)*16);
                    #pragma unroll
                    for (int kt = 0; kt < 8; kt++) {
                        unsigned a0, a1, a2, a3;
                        LDSM4(a0, a1, a2, a3, arow + (unsigned)(kt*32));
                        MMA16816(dA, a0, a1, a2, a3, bf[0][kt][0], bf[0][kt][1]);
                        MMA16816(dB, a0, a1, a2, a3, bf[1][kt][0], bf[1][kt][1]);
                    }
                    if ((l & 3) < 3) {
                        int r0 = 16*mt + (l >> 2);
                        int cc = 2*(l & 3);
                        *(float2*)(ScW + r0*6 + cc)           = make_float2(dA[0], dA[1]);
                        *(float2*)(ScW + (r0+8)*6 + cc)       = make_float2(dA[2], dA[3]);
                        *(float2*)(ScW + 384 + r0*6 + cc)     = make_float2(dB[0], dB[1]);
                        *(float2*)(ScW + 384 + (r0+8)*6 + cc) = make_float2(dB[2], dB[3]);
                    }
                }
                __syncwarp();

                float g0[6], g1[6];
                #pragma unroll
                for (int s = 0; s < 2; s++) {
                    const float* sc = ScW + s*384;
                    unsigned* wp = Wp + s*288;
                    float aa = s ? aaB : aaA;
                    float bb = s ? bbB : bbA;
                    float4 qaV = *(const float4*)(sc + 12*l);
                    float2 qbV = *(const float2*)(sc + 12*l + 4);
                    elemgrad(qaV.x, qaV.y, qaV.z, qaV.w, qbV.x, qbV.y, aa, bb, l2, g0);
                    float2 qcV = *(const float2*)(sc + 12*l + 6);
                    float4 qdV = *(const float4*)(sc + 12*l + 8);
                    elemgrad(qcV.x, qcV.y, qdV.x, qdV.y, qdV.z, qdV.w, aa, bb, l2, g1);
                    #pragma unroll
                    for (int n = 0; n < 6; n++)
                        wp[l*9 + n] = packg(g0[n], g1[n]);
                }
            }
            __syncwarp();

            // ---- Phase B (tensor bwd): accD += Ftile^T @ G' ----
            {
                #pragma unroll
                for (int kt = 0; kt < 4; kt++) {
                    unsigned bA0 = Wp[8*kt*9 + wb0];
                    unsigned bA1 = Wp[8*kt*9 + wb1];
                    unsigned bB0 = Wp[288 + 8*kt*9 + wb0];
                    unsigned bB1 = Wp[288 + 8*kt*9 + wb1];
                    unsigned abase = fsh + bwd_off + (unsigned)(16*kt*272);
                    #pragma unroll
                    for (int mt = 0; mt < 8; mt++) {
                        unsigned a0, a1, a2, a3;
                        LDSM4T(a0, a1, a2, a3, abase + (unsigned)(mt*32));
                        MMA16816(accD[0][mt], a0, a1, a2, a3, bA0, bA1);
                        MMA16816(accD[1][mt], a0, a1, a2, a3, bB0, bB1);
                    }
                }
            }

            CPASYNC_WAIT0();
            __syncthreads();
            gi++;
        }

        // ---- Phase C: mc = M @ C ----
        ull mca[2][3] = {{0,0,0},{0,0,0}};
        {
            #pragma unroll 2
            for (int q = 0; q < 16; q++) {
                const float* cqp = Cq + q*36;
                float4 a0 = *(const float4*)(cqp);
                float4 a1 = *(const float4*)(cqp + 4);
                float4 a2 = *(const float4*)(cqp + 8);
                float4 b0 = *(const float4*)(cqp + 16);
                float4 b1 = *(const float4*)(cqp + 20);
                float4 b2 = *(const float4*)(cqp + 24);
                float cA[12] = {a0.x,a0.y,a0.z,a0.w, a1.x,a1.y,a1.z,a1.w, a2.x,a2.y,a2.z,a2.w};
                float cB[12] = {b0.x,b0.y,b0.z,b0.w, b1.x,b1.y,b1.z,b1.w, b2.x,b2.y,b2.z,b2.w};
                #pragma unroll
                for (int i = 0; i < 4; i++) {
                    int kk = 4*q + i;
                    ull pm = *(const ull*)&g_Mp[kk*32 + l];
                    mca[0][0] = ffma2(pm, fdup(cA[i*3+0]), mca[0][0]);
                    mca[0][1] = ffma2(pm, fdup(cA[i*3+1]), mca[0][1]);
                    mca[0][2] = ffma2(pm, fdup(cA[i*3+2]), mca[0][2]);
                    mca[1][0] = ffma2(pm, fdup(cB[i*3+0]), mca[1][0]);
                    mca[1][1] = ffma2(pm, fdup(cB[i*3+1]), mca[1][1]);
                    mca[1][2] = ffma2(pm, fdup(cB[i*3+2]), mca[1][2]);
                }
            }
        }
        __syncwarp();

        // ---- per sample: extract D, combine, SGD update ----
        #pragma unroll
        for (int s = 0; s < 2; s++) {
            #pragma unroll
            for (int mt = 0; mt < 8; mt++) {
                if ((l & 3) < 3) {
                    int r0 = 16*mt + (l >> 2);
                    int n2 = 2*(l & 3);
                    *(float2*)(ScW + r0*6 + n2) =
                        make_float2(accD[s][mt][0]*GBACK, accD[s][mt][1]*GBACK);
                    *(float2*)(ScW + (r0+8)*6 + n2) =
                        make_float2(accD[s][mt][2]*GBACK, accD[s][mt][3]*GBACK);
                }
            }
            __syncwarp();
            float m0f, m1f;
            #pragma unroll
            for (int k = 0; k < 2; k++) {
                int kk = k ? k1 : k0;
                int slot = (qa + (k ? 8 : 0))*36 + s*16 + la3;
                #pragma unroll
                for (int j = 0; j < 3; j++) {
                    float dval = ScW[(2*kk)*6 + j] + ScW[(2*kk+1)*6 + 3 + j];
                    funpack(mca[s][j], m0f, m1f);
                    float m = k ? m1f : m0f;
                    float negwv = Ws[l*12 + s*6 + k*3 + j];
                    Cq[slot + j] = Cq[slot + j] - LRATE * (dval + m + negwv);
                }
            }
            __syncwarp();
        }
    }

    // ---- output (from Cq) ----
    #pragma unroll
    for (int s = 0; s < 2; s++) {
        float* op = out + (size_t)(sA + s) * (KN*3);
        #pragma unroll
        for (int k = 0; k < 2; k++) {
            int kk = k ? k1 : k0;
            int slot = (qa + (k ? 8 : 0))*36 + s*16 + la3;
            #pragma unroll
            for (int j = 0; j < 3; j++)
                op[kk*3 + j] = Cq[slot + j];
        }
    }
}

extern "C" void kernel_launch(void* const* d_in, const int* in_sizes, int n_in,
                              void* d_out, int out_size)
{
    const float* R_U     = (const float*)d_in[0];
    const float* alpha   = (const float*)d_in[1];
    const float* beta    = (const float*)d_in[2];
    const float* lambdas = (const float*)d_in[3];
    const float* B       = (const float*)d_in[4];
    const float* Bd      = (const float*)d_in[5];
    const float* Bdd     = (const float*)d_in[6];
    const float* Bddd    = (const float*)d_in[7];
    const float* Bpinv   = (const float*)d_in[8];

    cudaFuncSetAttribute(inner_opt_kernel,
                         cudaFuncAttributeMaxDynamicSharedMemorySize, SMEM_BYTES);

    prep_kernel<<<192, 256>>>(B, Bd, Bdd, Bddd, Bpinv, lambdas);
    init_kernel<<<NSAMP/(WARPS*2), 256>>>(R_U, lambdas);
    inner_opt_kernel<<<NSAMP/(WARPS*2), 256, SMEM_BYTES>>>(
        alpha, beta, lambdas, (float*)d_out);
}